// round 10
// baseline (speedup 1.0000x reference)
#include <cuda_runtime.h>
#include <cuda_fp16.h>
#include <mma.h>
#include <cstdint>

using namespace nvcuda;

#define CC 2048
#define HWN 4096
#define NCONVB 512
#define NSAMPB 128   // 16 img x 8 K-splits
#define NTHR 384
#define RING 8

// ---------------- device scratch ----------------
__device__ __half g_W1h[128*2048];
__device__ float g_W2t[128*128];     // transposed W2: [k][o]
__device__ float g_p1[128*512];      // [ch][block] transposed partials
__device__ float g_p2[128*512];
__device__ float g_mean[128];
__device__ float g_istd[128];
__device__ float g_hs8[8*1024*192];
__device__ float g_tf[1024*128];
__device__ float g_tw[1024];
__device__ float g_loss[16];

// ---------------- helpers ----------------
__device__ __forceinline__ uint32_t h2u(float x, float y) {
    __half2 h = __floats2half2_rn(x, y);
    return *reinterpret_cast<uint32_t*>(&h);
}
__device__ __forceinline__ uint32_t smem_u32(const void* p) {
    uint32_t a;
    asm("{ .reg .u64 t; cvta.to.shared.u64 t, %1; cvt.u32.u64 %0, t; }" : "=r"(a) : "l"(p));
    return a;
}
__device__ __forceinline__ void mbar_init(uint32_t a, uint32_t cnt) {
    asm volatile("mbarrier.init.shared.b64 [%0], %1;" :: "r"(a), "r"(cnt) : "memory");
}
__device__ __forceinline__ void mbar_arrive(uint32_t a) {
    asm volatile("mbarrier.arrive.shared.b64 _, [%0];" :: "r"(a) : "memory");
}
__device__ __forceinline__ void mbar_wait(uint32_t a, uint32_t par) {
    asm volatile(
        "{\n\t.reg .pred P;\n\tWL%=:\n\t"
        "mbarrier.try_wait.parity.acquire.cta.shared::cta.b64 P, [%0], %1, 0x989680;\n\t"
        "@P bra.uni WD%=;\n\tbra.uni WL%=;\n\tWD%=:\n\t}"
        :: "r"(a), "r"(par) : "memory");
}

// ---------------- prep: W1 -> half, W2 -> transposed ----------------
__global__ void k_prep(const float* __restrict__ W1, const float* __restrict__ W2) {
    if (blockIdx.x < 256) {
        int idx = blockIdx.x*256 + threadIdx.x;     // 65536 float4
        float4 v = reinterpret_cast<const float4*>(W1)[idx];
        uint2 u; u.x = h2u(v.x, v.y); u.y = h2u(v.z, v.w);
        *reinterpret_cast<uint2*>(g_W1h + idx*4) = u;
    } else {
        int idx = (blockIdx.x - 256)*256 + threadIdx.x;  // 16384 floats
        int o = idx >> 7, k = idx & 127;
        g_W2t[k*128 + o] = W2[idx];
    }
}

// smem: A ring 8 x [32k][136] half (8704 B) | W ring 8 x [128ch][40] half (10240 B)
#define A_STAGE 8704
#define W_BASE  (RING*A_STAGE)      // 69632
#define W_STAGE 10240
#define DYNB    (W_BASE + RING*W_STAGE)   // 151552

__global__ __launch_bounds__(NTHR, 1)
void k_fused(const float* __restrict__ feats, const float* __restrict__ W1,
             const float* __restrict__ Wa1,  const int* __restrict__ labels) {
    extern __shared__ char dynC[];
    float* dyn = (float*)dynC;
    __shared__ float r1[256], r2[256];
    __shared__ uint64_t mbar[2*RING];    // [0..7]=full, [8..15]=empty
    const int tid = threadIdx.x;

    if (blockIdx.x >= NCONVB) {
        // ============ sampled path: exact fp32 conv at 64 label==1 pixels ============
        const int sb = blockIdx.x - NCONVB;
        const int z = sb & 7;
        const int b = sb >> 3;
        float* Fs  = dyn;                    // [64][33]
        float* Ws2 = dyn + 64*33;            // [192][33]
        int*   pix = (int*)(dyn + 64*33 + 192*33);

        if (tid < 64) pix[tid] = 0;
        __syncthreads();
        if (tid < 32) {
            const int lane = tid;
            int probe = 0;
            #pragma unroll
            for (int i = lane; i < 64; i += 32) probe |= labels[2*(i*512)+1];
            unsigned any = __ballot_sync(0xffffffffu, probe != 0);
            const bool is64 = (any == 0u);
            const long long* L64 = (const long long*)labels;
            int base = 0;
            for (int c = 0; c < 128; c++) {
                if (base >= 64) break;
                int p = (c << 5) + lane;
                long long v = is64 ? L64[(size_t)b*HWN + p]
                                   : (long long)labels[(size_t)b*HWN + p];
                bool valid = (v == 1);
                unsigned m = __ballot_sync(0xffffffffu, valid);
                int pre = __popc(m & ((1u << lane) - 1u));
                if (valid && base + pre < 64) pix[base + pre] = p;
                base += __popc(m);
            }
        }
        __syncthreads();

        float acc[4][12];
        #pragma unroll
        for (int i = 0; i < 4; i++)
            #pragma unroll
            for (int j = 0; j < 12; j++) acc[i][j] = 0.f;

        const int pg = tid & 15;     // only meaningful for tid<256
        const int cg = tid >> 4;
        const size_t fb = (size_t)b*CC*HWN;
        const int kbase = z * 256;

        for (int chn = 0; chn < 8; chn++) {
            int k0 = kbase + chn*32;
            __syncthreads();
            for (int idx = tid; idx < 64*32; idx += NTHR) {
                int px = idx >> 5, kk = idx & 31;
                Fs[px*33 + kk] = feats[fb + (size_t)(k0+kk)*HWN + pix[px]];
            }
            for (int idx = tid; idx < 192*32; idx += NTHR) {
                int r = idx >> 5, kk = idx & 31;
                Ws2[r*33 + kk] = (r < 128) ? W1[r*CC + k0 + kk]
                                           : Wa1[(r-128)*CC + k0 + kk];
            }
            __syncthreads();
            if (tid < 256) {
                #pragma unroll 4
                for (int kk = 0; kk < 32; kk++) {
                    float fv[4];
                    #pragma unroll
                    for (int i = 0; i < 4; i++) fv[i] = Fs[(pg*4 + i)*33 + kk];
                    #pragma unroll
                    for (int j = 0; j < 12; j++) {
                        float w = Ws2[(cg*12 + j)*33 + kk];
                        #pragma unroll
                        for (int i = 0; i < 4; i++) acc[i][j] += fv[i]*w;
                    }
                }
            }
        }
        if (tid < 256) {
            #pragma unroll
            for (int i = 0; i < 4; i++)
                #pragma unroll
                for (int j = 0; j < 12; j++)
                    g_hs8[(size_t)z*196608 + (b*64 + pg*4 + i)*192 + cg*12 + j] = acc[i][j];
        }
        return;
    }

    // ===== conv1 stats: warp-specialized producer/consumer, f16 wmma M=128 N=128 =====
    const int cb = blockIdx.x;
    const int b  = cb >> 5;
    const int p0 = (cb & 31) * 128;
    const float* F = feats + (size_t)b*CC*HWN + p0;

    if (tid == 0) {
        #pragma unroll
        for (int s = 0; s < RING; s++) {
            mbar_init(smem_u32(&mbar[s]), 128);        // full: 128 producer arrivals
            mbar_init(smem_u32(&mbar[RING + s]), 256); // empty: 256 consumer arrivals
        }
    }
    __syncthreads();

    if (tid < 256) {
        // ---------------- consumers: 8 warps, tile 32px x 64ch ----------------
        const int wid = tid >> 5;
        const int wr  = wid & 3;
        const int wc  = wid >> 2;

        wmma::fragment<wmma::accumulator,16,16,16,half> acc[2][4];
        #pragma unroll
        for (int i = 0; i < 2; i++)
            #pragma unroll
            for (int j = 0; j < 4; j++) wmma::fill_fragment(acc[i][j], __float2half(0.f));

        for (int kc = 0; kc < 64; kc++) {
            const int s = kc & (RING-1);
            mbar_wait(smem_u32(&mbar[s]), (kc >> 3) & 1);
            const half* Ab = (const half*)(dynC + s*A_STAGE);
            const half* Wb = (const half*)(dynC + W_BASE + s*W_STAGE);
            #pragma unroll
            for (int ks = 0; ks < 32; ks += 16) {
                wmma::fragment<wmma::matrix_a,16,16,16,half,wmma::col_major> af[2];
                #pragma unroll
                for (int i = 0; i < 2; i++)
                    wmma::load_matrix_sync(af[i], Ab + ks*136 + wr*32 + i*16, 136);
                wmma::fragment<wmma::matrix_b,16,16,16,half,wmma::col_major> bf[4];
                #pragma unroll
                for (int j = 0; j < 4; j++)
                    wmma::load_matrix_sync(bf[j], Wb + (wc*64 + j*16)*40 + ks, 40);
                #pragma unroll
                for (int i = 0; i < 2; i++)
                    #pragma unroll
                    for (int j = 0; j < 4; j++)
                        wmma::mma_sync(acc[i][j], af[i], bf[j], acc[i][j]);
            }
            mbar_arrive(smem_u32(&mbar[RING + s]));
        }

        __syncthreads();
        // Epilogue: f16 acc -> smem -> per-channel sum/sumsq, transposed partials
        half* Cs16 = (half*)dynC;   // [128 px][136]
        #pragma unroll
        for (int i = 0; i < 2; i++)
            #pragma unroll
            for (int j = 0; j < 4; j++)
                wmma::store_matrix_sync(Cs16 + (wr*32 + i*16)*136 + wc*64 + j*16,
                                        acc[i][j], 136, wmma::mem_row_major);
        __syncthreads();
        {
            const int ch = tid & 127;
            const int sg = tid >> 7;
            float s = 0.f, s2 = 0.f;
            #pragma unroll 4
            for (int p = sg*64; p < sg*64 + 64; p++) {
                float v = __half2float(Cs16[p*136 + ch]);
                s += v; s2 += v*v;
            }
            r1[tid] = s; r2[tid] = s2;
        }
        __syncthreads();
        if (tid < 128) {
            g_p1[tid*512 + cb] = r1[tid] + r1[tid+128];
            g_p2[tid*512 + cb] = r2[tid] + r2[tid+128];
        }
    } else {
        // ---------------- producers: 128 threads, free-running fill loop ----------
        const int pt = tid - 256;

        float4 ra[8], rb[8];
        uint4  rw[4], rx[4];

        auto ldA = [&](int kc, float4* r) {
            const float* Fg = F + (size_t)(kc*32)*HWN;
            #pragma unroll
            for (int i = 0; i < 8; i++) {
                int slot = pt + i*128;
                int k = slot >> 5, px4 = (slot & 31) << 2;
                r[i] = *reinterpret_cast<const float4*>(Fg + (size_t)k*HWN + px4);
            }
        };
        auto ldW = [&](int kc, uint4* r) {
            const __half* Wg = g_W1h + kc*32;
            #pragma unroll
            for (int i = 0; i < 4; i++) {
                int slot = pt + i*128;
                int ch = slot >> 2, k8 = (slot & 3) << 3;
                r[i] = *reinterpret_cast<const uint4*>(Wg + ch*2048 + k8);
            }
        };
        auto stAW = [&](int kc, const float4* r, const uint4* w) {
            int s = kc & (RING-1);
            half* Ab = (half*)(dynC + s*A_STAGE);
            half* Wb = (half*)(dynC + W_BASE + s*W_STAGE);
            #pragma unroll
            for (int i = 0; i < 8; i++) {
                int slot = pt + i*128;
                int k = slot >> 5, px4 = (slot & 31) << 2;
                uint2 u; u.x = h2u(r[i].x, r[i].y); u.y = h2u(r[i].z, r[i].w);
                *reinterpret_cast<uint2*>(Ab + k*136 + px4) = u;
            }
            #pragma unroll
            for (int i = 0; i < 4; i++) {
                int slot = pt + i*128;
                int ch = slot >> 2, k8 = (slot & 3) << 3;
                *reinterpret_cast<uint4*>(Wb + ch*40 + k8) = w[i];
            }
        };

        ldA(0, ra); ldW(0, rw);
        for (int kc = 0; kc < 64; kc += 2) {
            ldA(kc+1, rb); ldW(kc+1, rx);
            {
                int s = kc & (RING-1);
                mbar_wait(smem_u32(&mbar[RING + s]), (((kc >> 3) & 1) ^ 1));
                stAW(kc, ra, rw);
                mbar_arrive(smem_u32(&mbar[s]));
            }
            if (kc + 2 < 64) { ldA(kc+2, ra); ldW(kc+2, rw); }
            {
                int kc1 = kc + 1;
                int s = kc1 & (RING-1);
                mbar_wait(smem_u32(&mbar[RING + s]), (((kc1 >> 3) & 1) ^ 1));
                stAW(kc1, rb, rx);
                mbar_arrive(smem_u32(&mbar[s]));
            }
        }
        __syncthreads();   // join consumers' pre-epilogue barrier
        __syncthreads();   // store_matrix barrier
        __syncthreads();   // reduction barrier
    }
}

// ---------------- stats: reduce per-block partials (grid 128 = one ch each) ----------
__global__ void k_stats() {
    __shared__ float sS[256], sS2[256];
    const int ch = blockIdx.x;
    const int t = threadIdx.x;
    if (ch == 0 && t < 16) g_loss[t] = 0.f;
    float S  = g_p1[ch*512 + t] + g_p1[ch*512 + t + 256];
    float S2 = g_p2[ch*512 + t] + g_p2[ch*512 + t + 256];
    sS[t] = S; sS2[t] = S2;
    __syncthreads();
    for (int s = 128; s > 0; s >>= 1) {
        if (t < s) { sS[t] += sS[t+s]; sS2[t] += sS2[t+s]; }
        __syncthreads();
    }
    if (t == 0) {
        float m   = sS[0] * (1.f/65536.f);
        float var = sS2[0] * (1.f/65536.f) - m*m;
        g_mean[ch] = m;
        g_istd[ch] = rsqrtf(var + 1e-5f);
    }
}

// ---------------- per-pixel: BN + conv2 (coalesced W2t) + normalize + attention -------
__global__ void k_proj(const float* __restrict__ b1, const float* __restrict__ gamma,
                       const float* __restrict__ beta, const float* __restrict__ b2,
                       const float* __restrict__ ba1, const float* __restrict__ Wa2,
                       const float* __restrict__ ba2) {
    __shared__ float xr[128];
    __shared__ float ar[64];
    __shared__ float red[128];
    const int t = threadIdx.x;
    const int pid = blockIdx.x;
    {
        float h = b1[t];
        #pragma unroll
        for (int z = 0; z < 8; z++) h += g_hs8[(size_t)z*196608 + pid*192 + t];
        float xn = (h - (g_mean[t] + b1[t])) * g_istd[t] * gamma[t] + beta[t];
        xr[t] = fmaxf(xn, 0.f);
    }
    if (t < 64) {
        float ha = 0.f;
        #pragma unroll
        for (int z = 0; z < 8; z++) ha += g_hs8[(size_t)z*196608 + pid*192 + 128 + t];
        ar[t] = fmaxf(ha + ba1[t], 0.f);
    }
    __syncthreads();

    float acc = b2[t];
    #pragma unroll 8
    for (int k = 0; k < 128; k++) acc += g_W2t[k*128 + t] * xr[k];

    red[t] = acc*acc;
    __syncthreads();
    for (int s = 64; s > 0; s >>= 1) { if (t < s) red[t] += red[t+s]; __syncthreads(); }
    float rinv = 1.f / fmaxf(sqrtf(red[0]), 1e-12f);
    g_tf[pid*128 + t] = acc * rinv;

    if (t < 32) {
        float z = Wa2[t]*ar[t] + Wa2[t+32]*ar[t+32];
        #pragma unroll
        for (int o = 16; o > 0; o >>= 1) z += __shfl_down_sync(0xffffffffu, z, o);
        if (t == 0) g_tw[pid] = 1.f / (1.f + expf(-(z + ba2[0])));
    }
}

// ---------------- contrastive loss (grid 64 = 4 row-blocks per image) ----------------
__global__ __launch_bounds__(256) void k_loss() {
    __shared__ float tf[64*128];
    __shared__ float tw[64];
    __shared__ float red[256];
    const int t = threadIdx.x;
    const int b  = blockIdx.x >> 2;
    const int rg = blockIdx.x & 3;

    #pragma unroll
    for (int i = 0; i < 8; i++)
        reinterpret_cast<float4*>(tf)[t + i*256] =
            reinterpret_cast<const float4*>(g_tf + b*8192)[t + i*256];
    if (t < 64) tw[t] = g_tw[b*64 + t];
    __syncthreads();

    const int lr = t >> 4;
    const int cg = t & 15;
    const int i  = rg*16 + lr;

    float s[4];
    {
        float a0 = 0.f, a1 = 0.f, a2 = 0.f, a3 = 0.f;
        const float4* fi = reinterpret_cast<const float4*>(tf + i*128);
        const float4* c0 = reinterpret_cast<const float4*>(tf + (cg*4+0)*128);
        const float4* c1 = reinterpret_cast<const float4*>(tf + (cg*4+1)*128);
        const float4* c2 = reinterpret_cast<const float4*>(tf + (cg*4+2)*128);
        const float4* c3 = reinterpret_cast<const float4*>(tf + (cg*4+3)*128);
        #pragma unroll 8
        for (int k4 = 0; k4 < 32; k4++) {
            float4 a = fi[k4];
            float4 v0 = c0[k4], v1 = c1[k4], v2 = c2[k4], v3 = c3[k4];
            a0 += a.x*v0.x + a.y*v0.y + a.z*v0.z + a.w*v0.w;
            a1 += a.x*v1.x + a.y*v1.y + a.z*v1.z + a.w*v1.w;
            a2 += a.x*v2.x + a.y*v2.y + a.z*v2.z + a.w*v2.w;
            a3 += a.x*v3.x + a.y*v3.y + a.z*v3.z + a.w*v3.w;
        }
        s[0] = a0*10.f; s[1] = a1*10.f; s[2] = a2*10.f; s[3] = a3*10.f;
    }
    float d = expf(s[0]) + expf(s[1]) + expf(s[2]) + expf(s[3]);
    d += __shfl_xor_sync(0xffffffffu, d, 1);
    d += __shfl_xor_sync(0xffffffffu, d, 2);
    d += __shfl_xor_sync(0xffffffffu, d, 4);
    d += __shfl_xor_sync(0xffffffffu, d, 8);

    float lacc = 0.f;
    float twi = tw[i];
    #pragma unroll
    for (int j = 0; j < 4; j++) {
        int jj = cg*4 + j;
        if (s[j] > 0.7f && jj != i)
            lacc += twi * tw[jj] * logf(expf(s[j])/d + 1e-10f);
    }
    red[t] = lacc;
    __syncthreads();
    for (int sft = 128; sft > 0; sft >>= 1) { if (t < sft) red[t] += red[t+sft]; __syncthreads(); }
    if (t == 0) atomicAdd(&g_loss[b], red[0]);
}

// ---------------- final: per-image normalize + mean * LOSS_WEIGHT ----------------
__global__ void k_final(float* out) {
    int t = threadIdx.x;
    float v = 0.f;
    if (t < 16) {
        float tsum = 0.f;
        for (int j = 0; j < 64; j++) tsum += g_tw[t*64 + j];
        v = -(0.1f/0.07f) * g_loss[t] / tsum;
    }
    #pragma unroll
    for (int o = 16; o > 0; o >>= 1) v += __shfl_down_sync(0xffffffffu, v, o);
    if (t == 0) out[0] = (v / 16.0f) * 0.1f;
}

// ---------------- launch ----------------
extern "C" void kernel_launch(void* const* d_in, const int* in_sizes, int n_in,
                              void* d_out, int out_size) {
    const float* feats = (const float*)d_in[0];
    const int*   labels= (const int*)d_in[1];
    const float* W1   = (const float*)d_in[2];
    const float* b1   = (const float*)d_in[3];
    const float* gamma= (const float*)d_in[4];
    const float* beta = (const float*)d_in[5];
    const float* W2   = (const float*)d_in[6];
    const float* b2   = (const float*)d_in[7];
    const float* Wa1  = (const float*)d_in[8];
    const float* ba1  = (const float*)d_in[9];
    const float* Wa2  = (const float*)d_in[10];
    const float* ba2  = (const float*)d_in[11];

    cudaFuncSetAttribute(k_fused, cudaFuncAttributeMaxDynamicSharedMemorySize, DYNB);

    k_prep<<<320, 256>>>(W1, W2);
    k_fused<<<NCONVB + NSAMPB, NTHR, DYNB>>>(feats, W1, Wa1, labels);
    k_stats<<<128, 256>>>();
    k_proj<<<1024, 128>>>(b1, gamma, beta, b2, ba1, Wa2, ba2);
    k_loss<<<64, 256>>>();
    k_final<<<1, 32>>>((float*)d_out);
}

// round 11
// speedup vs baseline: 1.1666x; 1.1666x over previous
#include <cuda_runtime.h>
#include <cuda_fp16.h>
#include <mma.h>
#include <cstdint>

using namespace nvcuda;

#define CC 2048
#define HWN 4096
#define NCONVB 512
#define NSAMPB 128   // 16 img x 8 K-splits

// ---------------- device scratch ----------------
__device__ __half g_W1h[128*2048];
__device__ float g_W2t[128*128];     // transposed W2: [k][o]
__device__ float g_p1[128*512];      // [ch][block] transposed partials
__device__ float g_p2[128*512];
__device__ float g_mean[128];
__device__ float g_istd[128];
__device__ float g_hs8[8*1024*192];
__device__ float g_tf[1024*128];
__device__ float g_tw[1024];
__device__ float g_loss[16];
__device__ int   g_done;
__device__ int   g_ticket;

// ---------------- helpers ----------------
__device__ __forceinline__ void cpasync16(void* s, const void* g) {
    unsigned sa = (unsigned)__cvta_generic_to_shared(s);
    asm volatile("cp.async.cg.shared.global [%0], [%1], 16;\n" :: "r"(sa), "l"(g));
}
__device__ __forceinline__ void cpcommit() { asm volatile("cp.async.commit_group;\n"); }
template<int N> __device__ __forceinline__ void cpwait() {
    asm volatile("cp.async.wait_group %0;\n" :: "n"(N));
}
__device__ __forceinline__ uint32_t h2u(float x, float y) {
    __half2 h = __floats2half2_rn(x, y);
    return *reinterpret_cast<uint32_t*>(&h);
}

// ---------------- prep: W1 -> half, W2 -> transposed, counters reset ----------------
__global__ void k_prep(const float* __restrict__ W1, const float* __restrict__ W2) {
    if (blockIdx.x == 0 && threadIdx.x < 18) {
        if (threadIdx.x < 16) g_loss[threadIdx.x] = 0.f;
        else if (threadIdx.x == 16) g_done = 0;
        else g_ticket = 0;
    }
    if (blockIdx.x < 256) {
        int idx = blockIdx.x*256 + threadIdx.x;     // 65536 float4
        float4 v = reinterpret_cast<const float4*>(W1)[idx];
        uint2 u; u.x = h2u(v.x, v.y); u.y = h2u(v.z, v.w);
        *reinterpret_cast<uint2*>(g_W1h + idx*4) = u;
    } else {
        int idx = (blockIdx.x - 256)*256 + threadIdx.x;  // 16384 floats
        int o = idx >> 7, k = idx & 127;
        g_W2t[k*128 + o] = W2[idx];
    }
}

// smem: A f16 2 x 8704 | W f16 4 x 10240 = 58368 B
#define DYNB 58368

__global__ __launch_bounds__(256, 2)
void k_fused(const float* __restrict__ feats, const float* __restrict__ W1,
             const float* __restrict__ Wa1,  const int* __restrict__ labels) {
    extern __shared__ char dynC[];
    float* dyn = (float*)dynC;
    __shared__ float r1[256], r2[256];
    const int tid = threadIdx.x;

    if (blockIdx.x < NSAMPB) {
        // ============ sampled path FIRST (wave-1 overlap): exact fp32 conv ============
        const int sb = blockIdx.x;
        const int z = sb & 7;
        const int b = sb >> 3;
        float* Fs  = dyn;                    // [64][33]
        float* Ws2 = dyn + 64*33;            // [192][33]
        int*   pix = (int*)(dyn + 64*33 + 192*33);

        if (tid < 64) pix[tid] = 0;
        __syncthreads();
        if (tid < 32) {
            const int lane = tid;
            int probe = 0;
            #pragma unroll
            for (int i = lane; i < 64; i += 32) probe |= labels[2*(i*512)+1];
            unsigned any = __ballot_sync(0xffffffffu, probe != 0);
            const bool is64 = (any == 0u);
            const long long* L64 = (const long long*)labels;
            int base = 0;
            for (int c = 0; c < 128; c++) {
                if (base >= 64) break;
                int p = (c << 5) + lane;
                long long v = is64 ? L64[(size_t)b*HWN + p]
                                   : (long long)labels[(size_t)b*HWN + p];
                bool valid = (v == 1);
                unsigned m = __ballot_sync(0xffffffffu, valid);
                int pre = __popc(m & ((1u << lane) - 1u));
                if (valid && base + pre < 64) pix[base + pre] = p;
                base += __popc(m);
            }
        }
        __syncthreads();

        float acc[4][12];
        #pragma unroll
        for (int i = 0; i < 4; i++)
            #pragma unroll
            for (int j = 0; j < 12; j++) acc[i][j] = 0.f;

        const int pg = tid & 15;
        const int cg = tid >> 4;
        const size_t fb = (size_t)b*CC*HWN;
        const int kbase = z * 256;

        for (int chn = 0; chn < 8; chn++) {
            int k0 = kbase + chn*32;
            __syncthreads();
            #pragma unroll
            for (int i = 0; i < 8; i++) {
                int idx = tid + i*256;
                int px = idx >> 5, kk = idx & 31;
                Fs[px*33 + kk] = feats[fb + (size_t)(k0+kk)*HWN + pix[px]];
            }
            #pragma unroll
            for (int i = 0; i < 24; i++) {
                int idx = tid + i*256;
                int r = idx >> 5, kk = idx & 31;
                Ws2[r*33 + kk] = (r < 128) ? W1[r*CC + k0 + kk]
                                           : Wa1[(r-128)*CC + k0 + kk];
            }
            __syncthreads();
            #pragma unroll 4
            for (int kk = 0; kk < 32; kk++) {
                float fv[4];
                #pragma unroll
                for (int i = 0; i < 4; i++) fv[i] = Fs[(pg*4 + i)*33 + kk];
                #pragma unroll
                for (int j = 0; j < 12; j++) {
                    float w = Ws2[(cg*12 + j)*33 + kk];
                    #pragma unroll
                    for (int i = 0; i < 4; i++) acc[i][j] += fv[i]*w;
                }
            }
        }
        #pragma unroll
        for (int i = 0; i < 4; i++)
            #pragma unroll
            for (int j = 0; j < 12; j++)
                g_hs8[(size_t)z*196608 + (b*64 + pg*4 + i)*192 + cg*12 + j] = acc[i][j];
        return;
    }

    // ===== conv1 stats: f16 wmma, M=128 x N=128; A = LDG->reg-convert->STS ===========
    const int cb = blockIdx.x - NSAMPB;
    const int b  = cb >> 5;
    const int p0 = (cb & 31) * 128;
    const float* F = feats + (size_t)b*CC*HWN + p0;

    const int wid = tid >> 5;
    const int wr  = wid & 3;    // 32-pixel group
    const int wc  = wid >> 2;   // 64-channel group

    wmma::fragment<wmma::accumulator,16,16,16,half> acc[2][4];
    #pragma unroll
    for (int i = 0; i < 2; i++)
        #pragma unroll
        for (int j = 0; j < 4; j++) wmma::fill_fragment(acc[i][j], __float2half(0.f));

    auto Ah = [&](int s) { return (half*)(dynC + s*8704); };             // [32k][136]
    auto Wh = [&](int s) { return (half*)(dynC + 17408 + s*10240); };    // [128ch][40]

    float4 ra[4];
    auto ldA = [&](int kc) {
        const float* Fg = F + (size_t)(kc*32)*HWN;
        #pragma unroll
        for (int i = 0; i < 4; i++) {
            int idx = tid + i*256;
            int k = idx >> 5, px4 = (idx & 31) << 2;
            ra[i] = *reinterpret_cast<const float4*>(Fg + (size_t)k*HWN + px4);
        }
    };
    auto stA = [&](int kc) {
        half* Ab = Ah(kc & 1);
        #pragma unroll
        for (int i = 0; i < 4; i++) {
            int idx = tid + i*256;
            int k = idx >> 5, px4 = (idx & 31) << 2;
            uint2 u; u.x = h2u(ra[i].x, ra[i].y); u.y = h2u(ra[i].z, ra[i].w);
            *reinterpret_cast<uint2*>(Ab + k*136 + px4) = u;
        }
    };
    auto issueW = [&](int kc) {
        half* W = Wh(kc & 3);
        const __half* Wg = g_W1h + kc*32;
        #pragma unroll
        for (int i = 0; i < 2; i++) {
            int idx = tid + i*256;
            int ch = idx >> 2, k8 = (idx & 3) << 3;
            cpasync16(W + ch*40 + k8, Wg + ch*2048 + k8);
        }
        cpcommit();
    };
    auto compute = [&](int kc) {
        const half* Ab = Ah(kc & 1);
        const half* Wb = Wh(kc & 3);
        #pragma unroll
        for (int ks = 0; ks < 32; ks += 16) {
            wmma::fragment<wmma::matrix_a,16,16,16,half,wmma::col_major> af[2];
            #pragma unroll
            for (int i = 0; i < 2; i++)
                wmma::load_matrix_sync(af[i], Ab + ks*136 + wr*32 + i*16, 136);
            wmma::fragment<wmma::matrix_b,16,16,16,half,wmma::col_major> bf[4];
            #pragma unroll
            for (int j = 0; j < 4; j++)
                wmma::load_matrix_sync(bf[j], Wb + (wc*64 + j*16)*40 + ks, 40);
            #pragma unroll
            for (int i = 0; i < 2; i++)
                #pragma unroll
                for (int j = 0; j < 4; j++)
                    wmma::mma_sync(acc[i][j], af[i], bf[j], acc[i][j]);
        }
    };

    issueW(0); issueW(1);
    ldA(0); stA(0);
    ldA(1);
    cpwait<1>();
    __syncthreads();

    for (int kc = 0; kc < 64; kc++) {
        if (kc + 1 < 64) stA(kc + 1);
        if (kc + 2 < 64) ldA(kc + 2);
        compute(kc);
        if (kc + 2 < 64) { issueW(kc + 2); cpwait<1>(); }
        else             { cpwait<0>(); }
        __syncthreads();
    }

    // Epilogue
    half* Cs16 = (half*)dynC;   // [128 px][136]
    #pragma unroll
    for (int i = 0; i < 2; i++)
        #pragma unroll
        for (int j = 0; j < 4; j++)
            wmma::store_matrix_sync(Cs16 + (wr*32 + i*16)*136 + wc*64 + j*16,
                                    acc[i][j], 136, wmma::mem_row_major);
    __syncthreads();
    {
        const int ch = tid & 127;
        const int sg = tid >> 7;
        float s = 0.f, s2 = 0.f;
        #pragma unroll 4
        for (int p = sg*64; p < sg*64 + 64; p++) {
            float v = __half2float(Cs16[p*136 + ch]);
            s += v; s2 += v*v;
        }
        r1[tid] = s; r2[tid] = s2;
        __syncthreads();
        if (tid < 128) {
            g_p1[tid*512 + cb] = r1[tid] + r1[tid+128];
            g_p2[tid*512 + cb] = r2[tid] + r2[tid+128];
        }
    }
}

// ---------------- tail1: stats (blocks 0..127) + proj (blocks 128..1151) -------------
__global__ __launch_bounds__(128) void k_tail1(
        const float* __restrict__ b1, const float* __restrict__ gamma,
        const float* __restrict__ beta, const float* __restrict__ b2,
        const float* __restrict__ ba1, const float* __restrict__ Wa2,
        const float* __restrict__ ba2) {
    const int t = threadIdx.x;

    if (blockIdx.x < 128) {
        // ---- stats for channel = blockIdx.x ----
        __shared__ float sS[128], sS2[128];
        const int ch = blockIdx.x;
        float S = 0.f, S2 = 0.f;
        for (int i = t; i < 512; i += 128) {
            S  += g_p1[ch*512 + i];
            S2 += g_p2[ch*512 + i];
        }
        sS[t] = S; sS2[t] = S2;
        __syncthreads();
        for (int s = 64; s > 0; s >>= 1) {
            if (t < s) { sS[t] += sS[t+s]; sS2[t] += sS2[t+s]; }
            __syncthreads();
        }
        if (t == 0) {
            float m   = sS[0] * (1.f/65536.f);
            float var = sS2[0] * (1.f/65536.f) - m*m;
            g_mean[ch] = m;
            g_istd[ch] = rsqrtf(var + 1e-5f);
            __threadfence();
            atomicAdd(&g_done, 1);
        }
        return;
    }

    // ---- proj for pixel pid = blockIdx.x - 128 ----
    const int pid = blockIdx.x - 128;
    __shared__ float xr[128];
    __shared__ float ar[64];
    __shared__ float red[128];

    if (t == 0) {
        while (atomicAdd(&g_done, 0) < 128) __nanosleep(200);
    }
    __syncthreads();

    {
        float h = b1[t];
        #pragma unroll
        for (int z = 0; z < 8; z++) h += g_hs8[(size_t)z*196608 + pid*192 + t];
        float xn = (h - (g_mean[t] + b1[t])) * g_istd[t] * gamma[t] + beta[t];
        xr[t] = fmaxf(xn, 0.f);
    }
    if (t < 64) {
        float ha = 0.f;
        #pragma unroll
        for (int z = 0; z < 8; z++) ha += g_hs8[(size_t)z*196608 + pid*192 + 128 + t];
        ar[t] = fmaxf(ha + ba1[t], 0.f);
    }
    __syncthreads();

    float acc = b2[t];
    #pragma unroll 8
    for (int k = 0; k < 128; k++) acc += g_W2t[k*128 + t] * xr[k];

    red[t] = acc*acc;
    __syncthreads();
    for (int s = 64; s > 0; s >>= 1) { if (t < s) red[t] += red[t+s]; __syncthreads(); }
    float rinv = 1.f / fmaxf(sqrtf(red[0]), 1e-12f);
    g_tf[pid*128 + t] = acc * rinv;

    if (t < 32) {
        float z = Wa2[t]*ar[t] + Wa2[t+32]*ar[t+32];
        #pragma unroll
        for (int o = 16; o > 0; o >>= 1) z += __shfl_down_sync(0xffffffffu, z, o);
        if (t == 0) g_tw[pid] = 1.f / (1.f + expf(-(z + ba2[0])));
    }
}

// ---------------- tail2: loss (64 blocks) + final (ticket) ----------------
__global__ __launch_bounds__(256) void k_tail2(float* out) {
    __shared__ float tf[64*128];
    __shared__ float tw[64];
    __shared__ float red[256];
    const int t = threadIdx.x;
    const int b  = blockIdx.x >> 2;
    const int rg = blockIdx.x & 3;

    #pragma unroll
    for (int i = 0; i < 8; i++)
        reinterpret_cast<float4*>(tf)[t + i*256] =
            reinterpret_cast<const float4*>(g_tf + b*8192)[t + i*256];
    if (t < 64) tw[t] = g_tw[b*64 + t];
    __syncthreads();

    const int lr = t >> 4;
    const int cg = t & 15;
    const int i  = rg*16 + lr;

    float s[4];
    {
        float a0 = 0.f, a1 = 0.f, a2 = 0.f, a3 = 0.f;
        const float4* fi = reinterpret_cast<const float4*>(tf + i*128);
        const float4* c0 = reinterpret_cast<const float4*>(tf + (cg*4+0)*128);
        const float4* c1 = reinterpret_cast<const float4*>(tf + (cg*4+1)*128);
        const float4* c2 = reinterpret_cast<const float4*>(tf + (cg*4+2)*128);
        const float4* c3 = reinterpret_cast<const float4*>(tf + (cg*4+3)*128);
        #pragma unroll 8
        for (int k4 = 0; k4 < 32; k4++) {
            float4 a = fi[k4];
            float4 v0 = c0[k4], v1 = c1[k4], v2 = c2[k4], v3 = c3[k4];
            a0 += a.x*v0.x + a.y*v0.y + a.z*v0.z + a.w*v0.w;
            a1 += a.x*v1.x + a.y*v1.y + a.z*v1.z + a.w*v1.w;
            a2 += a.x*v2.x + a.y*v2.y + a.z*v2.z + a.w*v2.w;
            a3 += a.x*v3.x + a.y*v3.y + a.z*v3.z + a.w*v3.w;
        }
        s[0] = a0*10.f; s[1] = a1*10.f; s[2] = a2*10.f; s[3] = a3*10.f;
    }
    float d = expf(s[0]) + expf(s[1]) + expf(s[2]) + expf(s[3]);
    d += __shfl_xor_sync(0xffffffffu, d, 1);
    d += __shfl_xor_sync(0xffffffffu, d, 2);
    d += __shfl_xor_sync(0xffffffffu, d, 4);
    d += __shfl_xor_sync(0xffffffffu, d, 8);

    float lacc = 0.f;
    float twi = tw[i];
    #pragma unroll
    for (int j = 0; j < 4; j++) {
        int jj = cg*4 + j;
        if (s[j] > 0.7f && jj != i)
            lacc += twi * tw[jj] * logf(expf(s[j])/d + 1e-10f);
    }
    red[t] = lacc;
    __syncthreads();
    for (int sft = 128; sft > 0; sft >>= 1) { if (t < sft) red[t] += red[t+sft]; __syncthreads(); }

    if (t == 0) {
        atomicAdd(&g_loss[b], red[0]);
        __threadfence();
        int tk = atomicAdd(&g_ticket, 1);
        if (tk == 63) {
            // last block: finalize
            float total = 0.f;
            for (int img = 0; img < 16; img++) {
                float tsum = 0.f;
                for (int j = 0; j < 64; j++) tsum += g_tw[img*64 + j];
                float lv = atomicAdd(&g_loss[img], 0.f);   // ordered read
                total += -(0.1f/0.07f) * lv / tsum;
            }
            out[0] = (total / 16.0f) * 0.1f;
        }
    }
}

// ---------------- launch ----------------
extern "C" void kernel_launch(void* const* d_in, const int* in_sizes, int n_in,
                              void* d_out, int out_size) {
    const float* feats = (const float*)d_in[0];
    const int*   labels= (const int*)d_in[1];
    const float* W1   = (const float*)d_in[2];
    const float* b1   = (const float*)d_in[3];
    const float* gamma= (const float*)d_in[4];
    const float* beta = (const float*)d_in[5];
    const float* W2   = (const float*)d_in[6];
    const float* b2   = (const float*)d_in[7];
    const float* Wa1  = (const float*)d_in[8];
    const float* ba1  = (const float*)d_in[9];
    const float* Wa2  = (const float*)d_in[10];
    const float* ba2  = (const float*)d_in[11];

    cudaFuncSetAttribute(k_fused, cudaFuncAttributeMaxDynamicSharedMemorySize, DYNB);

    k_prep<<<320, 256>>>(W1, W2);
    k_fused<<<NSAMPB + NCONVB, 256, DYNB>>>(feats, W1, Wa1, labels);
    k_tail1<<<1152, 128>>>(b1, gamma, beta, b2, ba1, Wa2, ba2);
    k_tail2<<<64, 256>>>((float*)d_out);
}

// round 12
// speedup vs baseline: 1.3270x; 1.1375x over previous
#include <cuda_runtime.h>
#include <cuda_fp16.h>
#include <mma.h>
#include <cstdint>

using namespace nvcuda;

#define CC 2048
#define HWN 4096
#define NCONVB 512
#define NSAMPB 128   // 16 img x 8 K-splits

// ---------------- device scratch ----------------
__device__ __half g_W1h[128*2048];
__device__ float g_W2t[128*128];     // transposed W2: [k][o]
__device__ float g_p1[128*512];      // [ch][block] transposed partials
__device__ float g_p2[128*512];
__device__ float g_mean[128];
__device__ float g_istd[128];
__device__ float g_hs8[8*1024*192];  // 8 K-split partials
__device__ float g_hs[1024*192];     // reduced (contiguous per pixel)
__device__ float g_tf[1024*128];
__device__ float g_tw[1024];
__device__ float g_loss[16];

// ---------------- helpers ----------------
__device__ __forceinline__ void cpasync16(void* s, const void* g) {
    unsigned sa = (unsigned)__cvta_generic_to_shared(s);
    asm volatile("cp.async.cg.shared.global [%0], [%1], 16;\n" :: "r"(sa), "l"(g));
}
__device__ __forceinline__ void cpcommit() { asm volatile("cp.async.commit_group;\n"); }
template<int N> __device__ __forceinline__ void cpwait() {
    asm volatile("cp.async.wait_group %0;\n" :: "n"(N));
}
__device__ __forceinline__ uint32_t h2u(float x, float y) {
    __half2 h = __floats2half2_rn(x, y);
    return *reinterpret_cast<uint32_t*>(&h);
}

// ---------------- prep: W1 -> half, W2 -> transposed ----------------
__global__ void k_prep(const float* __restrict__ W1, const float* __restrict__ W2) {
    if (blockIdx.x < 256) {
        int idx = blockIdx.x*256 + threadIdx.x;     // 65536 float4
        float4 v = reinterpret_cast<const float4*>(W1)[idx];
        uint2 u; u.x = h2u(v.x, v.y); u.y = h2u(v.z, v.w);
        *reinterpret_cast<uint2*>(g_W1h + idx*4) = u;
    } else {
        int idx = (blockIdx.x - 256)*256 + threadIdx.x;  // 16384 floats
        int o = idx >> 7, k = idx & 127;
        g_W2t[k*128 + o] = W2[idx];
    }
}

// smem: A f16 2 x 8704 | W f16 4 x 10240 = 58368 B
#define DYNB 58368

__global__ __launch_bounds__(256, 2)
void k_fused(const float* __restrict__ feats, const float* __restrict__ W1,
             const float* __restrict__ Wa1,  const int* __restrict__ labels) {
    extern __shared__ char dynC[];
    float* dyn = (float*)dynC;
    __shared__ float r1[256], r2[256];
    const int tid = threadIdx.x;

    if (blockIdx.x >= NCONVB) {
        // ============ sampled path: exact fp32 conv at 64 label==1 pixels ============
        const int sb = blockIdx.x - NCONVB;
        const int z = sb & 7;
        const int b = sb >> 3;
        float* Fs  = dyn;                    // [64][33]
        float* Ws2 = dyn + 64*33;            // [192][33]
        int*   pix = (int*)(dyn + 64*33 + 192*33);

        if (tid < 64) pix[tid] = 0;
        __syncthreads();
        if (tid < 32) {
            const int lane = tid;
            int probe = 0;
            #pragma unroll
            for (int i = lane; i < 64; i += 32) probe |= labels[2*(i*512)+1];
            unsigned any = __ballot_sync(0xffffffffu, probe != 0);
            const bool is64 = (any == 0u);
            const long long* L64 = (const long long*)labels;
            int base = 0;
            for (int c = 0; c < 128; c++) {
                if (base >= 64) break;
                int p = (c << 5) + lane;
                long long v = is64 ? L64[(size_t)b*HWN + p]
                                   : (long long)labels[(size_t)b*HWN + p];
                bool valid = (v == 1);
                unsigned m = __ballot_sync(0xffffffffu, valid);
                int pre = __popc(m & ((1u << lane) - 1u));
                if (valid && base + pre < 64) pix[base + pre] = p;
                base += __popc(m);
            }
        }
        __syncthreads();

        float acc[4][12];
        #pragma unroll
        for (int i = 0; i < 4; i++)
            #pragma unroll
            for (int j = 0; j < 12; j++) acc[i][j] = 0.f;

        const int pg = tid & 15;
        const int cg = tid >> 4;
        const size_t fb = (size_t)b*CC*HWN;
        const int kbase = z * 256;

        for (int chn = 0; chn < 8; chn++) {
            int k0 = kbase + chn*32;
            __syncthreads();
            #pragma unroll
            for (int i = 0; i < 8; i++) {
                int idx = tid + i*256;
                int px = idx >> 5, kk = idx & 31;
                Fs[px*33 + kk] = feats[fb + (size_t)(k0+kk)*HWN + pix[px]];
            }
            #pragma unroll
            for (int i = 0; i < 24; i++) {
                int idx = tid + i*256;
                int r = idx >> 5, kk = idx & 31;
                Ws2[r*33 + kk] = (r < 128) ? W1[r*CC + k0 + kk]
                                           : Wa1[(r-128)*CC + k0 + kk];
            }
            __syncthreads();
            #pragma unroll 4
            for (int kk = 0; kk < 32; kk++) {
                float fv[4];
                #pragma unroll
                for (int i = 0; i < 4; i++) fv[i] = Fs[(pg*4 + i)*33 + kk];
                #pragma unroll
                for (int j = 0; j < 12; j++) {
                    float w = Ws2[(cg*12 + j)*33 + kk];
                    #pragma unroll
                    for (int i = 0; i < 4; i++) acc[i][j] += fv[i]*w;
                }
            }
        }
        #pragma unroll
        for (int i = 0; i < 4; i++)
            #pragma unroll
            for (int j = 0; j < 12; j++)
                g_hs8[(size_t)z*196608 + (b*64 + pg*4 + i)*192 + cg*12 + j] = acc[i][j];
        return;
    }

    // ===== conv1 stats: f16 wmma, M=128 x N=128; A = LDG->reg-convert->STS ===========
    const int cb = blockIdx.x;
    const int b  = cb >> 5;
    const int p0 = (cb & 31) * 128;
    const float* F = feats + (size_t)b*CC*HWN + p0;

    const int wid = tid >> 5;
    const int wr  = wid & 3;    // 32-pixel group
    const int wc  = wid >> 2;   // 64-channel group

    wmma::fragment<wmma::accumulator,16,16,16,half> acc[2][4];
    #pragma unroll
    for (int i = 0; i < 2; i++)
        #pragma unroll
        for (int j = 0; j < 4; j++) wmma::fill_fragment(acc[i][j], __float2half(0.f));

    auto Ah = [&](int s) { return (half*)(dynC + s*8704); };             // [32k][136]
    auto Wh = [&](int s) { return (half*)(dynC + 17408 + s*10240); };    // [128ch][40]

    float4 ra[4];
    auto ldA = [&](int kc) {
        const float* Fg = F + (size_t)(kc*32)*HWN;
        #pragma unroll
        for (int i = 0; i < 4; i++) {
            int idx = tid + i*256;
            int k = idx >> 5, px4 = (idx & 31) << 2;
            ra[i] = *reinterpret_cast<const float4*>(Fg + (size_t)k*HWN + px4);
        }
    };
    auto stA = [&](int kc) {
        half* Ab = Ah(kc & 1);
        #pragma unroll
        for (int i = 0; i < 4; i++) {
            int idx = tid + i*256;
            int k = idx >> 5, px4 = (idx & 31) << 2;
            uint2 u; u.x = h2u(ra[i].x, ra[i].y); u.y = h2u(ra[i].z, ra[i].w);
            *reinterpret_cast<uint2*>(Ab + k*136 + px4) = u;
        }
    };
    auto issueW = [&](int kc) {
        half* W = Wh(kc & 3);
        const __half* Wg = g_W1h + kc*32;
        #pragma unroll
        for (int i = 0; i < 2; i++) {
            int idx = tid + i*256;
            int ch = idx >> 2, k8 = (idx & 3) << 3;
            cpasync16(W + ch*40 + k8, Wg + ch*2048 + k8);
        }
        cpcommit();
    };
    auto compute = [&](int kc) {
        const half* Ab = Ah(kc & 1);
        const half* Wb = Wh(kc & 3);
        #pragma unroll
        for (int ks = 0; ks < 32; ks += 16) {
            wmma::fragment<wmma::matrix_a,16,16,16,half,wmma::col_major> af[2];
            #pragma unroll
            for (int i = 0; i < 2; i++)
                wmma::load_matrix_sync(af[i], Ab + ks*136 + wr*32 + i*16, 136);
            wmma::fragment<wmma::matrix_b,16,16,16,half,wmma::col_major> bf[4];
            #pragma unroll
            for (int j = 0; j < 4; j++)
                wmma::load_matrix_sync(bf[j], Wb + (wc*64 + j*16)*40 + ks, 40);
            #pragma unroll
            for (int i = 0; i < 2; i++)
                #pragma unroll
                for (int j = 0; j < 4; j++)
                    wmma::mma_sync(acc[i][j], af[i], bf[j], acc[i][j]);
        }
    };

    issueW(0); issueW(1);
    ldA(0); stA(0);
    ldA(1);
    cpwait<1>();
    __syncthreads();

    for (int kc = 0; kc < 64; kc++) {
        if (kc + 1 < 64) stA(kc + 1);
        if (kc + 2 < 64) ldA(kc + 2);
        compute(kc);
        if (kc + 2 < 64) { issueW(kc + 2); cpwait<1>(); }
        else             { cpwait<0>(); }
        __syncthreads();
    }

    // Epilogue
    half* Cs16 = (half*)dynC;   // [128 px][136]
    #pragma unroll
    for (int i = 0; i < 2; i++)
        #pragma unroll
        for (int j = 0; j < 4; j++)
            wmma::store_matrix_sync(Cs16 + (wr*32 + i*16)*136 + wc*64 + j*16,
                                    acc[i][j], 136, wmma::mem_row_major);
    __syncthreads();
    {
        const int ch = tid & 127;
        const int sg = tid >> 7;
        float s = 0.f, s2 = 0.f;
        #pragma unroll 4
        for (int p = sg*64; p < sg*64 + 64; p++) {
            float v = __half2float(Cs16[p*136 + ch]);
            s += v; s2 += v*v;
        }
        r1[tid] = s; r2[tid] = s2;
        __syncthreads();
        if (tid < 128) {
            g_p1[tid*512 + cb] = r1[tid] + r1[tid+128];
            g_p2[tid*512 + cb] = r2[tid] + r2[tid+128];
        }
    }
}

// ---------------- stats (blocks 0..127) + hs8 reduce (blocks 128..895) ----------------
__global__ __launch_bounds__(256) void k_stats() {
    const int t = threadIdx.x;
    if (blockIdx.x < 128) {
        __shared__ float sS[256], sS2[256];
        const int ch = blockIdx.x;
        if (ch == 0 && t < 16) g_loss[t] = 0.f;
        float S  = g_p1[ch*512 + t] + g_p1[ch*512 + t + 256];
        float S2 = g_p2[ch*512 + t] + g_p2[ch*512 + t + 256];
        sS[t] = S; sS2[t] = S2;
        __syncthreads();
        for (int s = 128; s > 0; s >>= 1) {
            if (t < s) { sS[t] += sS[t+s]; sS2[t] += sS2[t+s]; }
            __syncthreads();
        }
        if (t == 0) {
            float m   = sS[0] * (1.f/65536.f);
            float var = sS2[0] * (1.f/65536.f) - m*m;
            g_mean[ch] = m;
            g_istd[ch] = rsqrtf(var + 1e-5f);
        }
        return;
    }
    // reduce 8 K-split partials into contiguous g_hs (same order as before: z=0..7)
    int o = (blockIdx.x - 128)*256 + t;    // < 196608
    float h = g_hs8[o];
    #pragma unroll
    for (int z = 1; z < 8; z++) h += g_hs8[(size_t)z*196608 + o];
    g_hs[o] = h;
}

// ---------------- per-pixel: BN + conv2 (coalesced W2t) + normalize + attention -------
__global__ void k_proj(const float* __restrict__ b1, const float* __restrict__ gamma,
                       const float* __restrict__ beta, const float* __restrict__ b2,
                       const float* __restrict__ ba1, const float* __restrict__ Wa2,
                       const float* __restrict__ ba2) {
    __shared__ float xr[128];
    __shared__ float ar[64];
    __shared__ float red[128];
    const int t = threadIdx.x;
    const int pid = blockIdx.x;
    {
        float h = g_hs[pid*192 + t] + b1[t];
        float xn = (h - (g_mean[t] + b1[t])) * g_istd[t] * gamma[t] + beta[t];
        xr[t] = fmaxf(xn, 0.f);
    }
    if (t < 64) ar[t] = fmaxf(g_hs[pid*192 + 128 + t] + ba1[t], 0.f);
    __syncthreads();

    float acc = b2[t];
    #pragma unroll 8
    for (int k = 0; k < 128; k++) acc += g_W2t[k*128 + t] * xr[k];

    red[t] = acc*acc;
    __syncthreads();
    for (int s = 64; s > 0; s >>= 1) { if (t < s) red[t] += red[t+s]; __syncthreads(); }
    float rinv = 1.f / fmaxf(sqrtf(red[0]), 1e-12f);
    g_tf[pid*128 + t] = acc * rinv;

    if (t < 32) {
        float z = Wa2[t]*ar[t] + Wa2[t+32]*ar[t+32];
        #pragma unroll
        for (int o = 16; o > 0; o >>= 1) z += __shfl_down_sync(0xffffffffu, z, o);
        if (t == 0) g_tw[pid] = 1.f / (1.f + expf(-(z + ba2[0])));
    }
}

// ---------------- contrastive loss: row-parallel, grid 128 (8 rows/block) -------------
__global__ __launch_bounds__(256) void k_loss() {
    __shared__ float tf[64*132];   // ld 132: float4 phases bank-conflict-free
    __shared__ float tw[64];
    const int t = threadIdx.x;
    const int b  = blockIdx.x >> 3;
    const int rg = blockIdx.x & 7;
    const int wid = t >> 5;
    const int lane = t & 31;

    #pragma unroll
    for (int i = 0; i < 8; i++) {
        int idx = t + i*256;               // float4 index < 2048
        int row = idx >> 5, c4 = (idx & 31) << 2;
        float4 v = reinterpret_cast<const float4*>(g_tf + b*8192)[idx];
        *reinterpret_cast<float4*>(tf + row*132 + c4) = v;
    }
    if (t < 64) tw[t] = g_tw[b*64 + t];
    __syncthreads();

    const int i = rg*8 + wid;              // this warp's row
    const int j0 = lane, j1 = lane + 32;   // this lane's two columns

    float a0 = 0.f, a1 = 0.f;
    const float4* fi = reinterpret_cast<const float4*>(tf + i*132);
    const float4* c0 = reinterpret_cast<const float4*>(tf + j0*132);
    const float4* c1 = reinterpret_cast<const float4*>(tf + j1*132);
    #pragma unroll 8
    for (int k4 = 0; k4 < 32; k4++) {
        float4 a = fi[k4];                 // broadcast
        float4 v0 = c0[k4], v1 = c1[k4];
        a0 += a.x*v0.x + a.y*v0.y + a.z*v0.z + a.w*v0.w;
        a1 += a.x*v1.x + a.y*v1.y + a.z*v1.z + a.w*v1.w;
    }
    float s0 = a0*10.f, s1 = a1*10.f;
    float e0 = expf(s0), e1 = expf(s1);
    float d = e0 + e1;
    #pragma unroll
    for (int o = 16; o > 0; o >>= 1) d += __shfl_xor_sync(0xffffffffu, d, o);

    float twi = tw[i];
    float lacc = 0.f;
    if (s0 > 0.7f && j0 != i) lacc += twi * tw[j0] * logf(e0/d + 1e-10f);
    if (s1 > 0.7f && j1 != i) lacc += twi * tw[j1] * logf(e1/d + 1e-10f);
    #pragma unroll
    for (int o = 16; o > 0; o >>= 1) lacc += __shfl_xor_sync(0xffffffffu, lacc, o);
    if (lane == 0) atomicAdd(&g_loss[b], lacc);
}

// ---------------- final: per-image normalize + mean * LOSS_WEIGHT ----------------
__global__ void k_final(float* out) {
    int t = threadIdx.x;
    float v = 0.f;
    if (t < 16) {
        float tsum = 0.f;
        for (int j = 0; j < 64; j++) tsum += g_tw[t*64 + j];
        v = -(0.1f/0.07f) * g_loss[t] / tsum;
    }
    #pragma unroll
    for (int o = 16; o > 0; o >>= 1) v += __shfl_down_sync(0xffffffffu, v, o);
    if (t == 0) out[0] = (v / 16.0f) * 0.1f;
}

// ---------------- launch ----------------
extern "C" void kernel_launch(void* const* d_in, const int* in_sizes, int n_in,
                              void* d_out, int out_size) {
    const float* feats = (const float*)d_in[0];
    const int*   labels= (const int*)d_in[1];
    const float* W1   = (const float*)d_in[2];
    const float* b1   = (const float*)d_in[3];
    const float* gamma= (const float*)d_in[4];
    const float* beta = (const float*)d_in[5];
    const float* W2   = (const float*)d_in[6];
    const float* b2   = (const float*)d_in[7];
    const float* Wa1  = (const float*)d_in[8];
    const float* ba1  = (const float*)d_in[9];
    const float* Wa2  = (const float*)d_in[10];
    const float* ba2  = (const float*)d_in[11];

    cudaFuncSetAttribute(k_fused, cudaFuncAttributeMaxDynamicSharedMemorySize, DYNB);

    k_prep<<<320, 256>>>(W1, W2);
    k_fused<<<NCONVB + NSAMPB, 256, DYNB>>>(feats, W1, Wa1, labels);
    k_stats<<<896, 256>>>();
    k_proj<<<1024, 128>>>(b1, gamma, beta, b2, ba1, Wa2, ba2);
    k_loss<<<128, 256>>>();
    k_final<<<1, 32>>>((float*)d_out);
}

// round 13
// speedup vs baseline: 1.4957x; 1.1272x over previous
#include <cuda_runtime.h>
#include <cuda_fp16.h>
#include <mma.h>
#include <cstdint>

using namespace nvcuda;

#define CC 2048
#define HWN 4096
#define NCONVB 512
#define NSAMPB 128   // 16 img x 8 K-splits

// ---------------- device scratch ----------------
__device__ __half g_W1h[128*2048];
__device__ float g_W2t[128*128];
__device__ float g_p1[128*512];
__device__ float g_p2[128*512];
__device__ float g_mean[128];
__device__ float g_istd[128];
__device__ float g_hs8[8*1024*192];
__device__ float g_hs[1024*192];
__device__ float g_tf[1024*128];
__device__ float g_tw[1024];
__device__ float g_loss[16];

// ---------------- helpers ----------------
__device__ __forceinline__ void cpasync16(void* s, const void* g) {
    unsigned sa = (unsigned)__cvta_generic_to_shared(s);
    asm volatile("cp.async.cg.shared.global [%0], [%1], 16;\n" :: "r"(sa), "l"(g));
}
__device__ __forceinline__ void cpcommit() { asm volatile("cp.async.commit_group;\n"); }
template<int N> __device__ __forceinline__ void cpwait() {
    asm volatile("cp.async.wait_group %0;\n" :: "n"(N));
}
__device__ __forceinline__ uint32_t h2u(float x, float y) {
    __half2 h = __floats2half2_rn(x, y);
    return *reinterpret_cast<uint32_t*>(&h);
}

// ---------------- prep: W1 -> half, W2 -> transposed ----------------
__global__ void k_prep(const float* __restrict__ W1, const float* __restrict__ W2) {
    if (blockIdx.x < 256) {
        int idx = blockIdx.x*256 + threadIdx.x;
        float4 v = reinterpret_cast<const float4*>(W1)[idx];
        uint2 u; u.x = h2u(v.x, v.y); u.y = h2u(v.z, v.w);
        *reinterpret_cast<uint2*>(g_W1h + idx*4) = u;
    } else {
        int idx = (blockIdx.x - 256)*256 + threadIdx.x;
        int o = idx >> 7, k = idx & 127;
        g_W2t[k*128 + o] = W2[idx];
    }
}

// smem: A f16 2 x [64k][136] (17408 B) | W f16 3 x [128ch][72] (18432 B) = 90112 B
#define A_STG 17408
#define W_OFF 34816
#define W_STG 18432
#define DYNB  90112

__global__ __launch_bounds__(256, 2)
void k_fused(const float* __restrict__ feats, const float* __restrict__ W1,
             const float* __restrict__ Wa1,  const int* __restrict__ labels) {
    extern __shared__ char dynC[];
    float* dyn = (float*)dynC;
    __shared__ float r1[256], r2[256];
    const int tid = threadIdx.x;

    if (blockIdx.x < NSAMPB) {
        // ============ sampled path FIRST: exact fp32 conv at 64 label==1 pixels ======
        const int sb = blockIdx.x;
        const int z = sb & 7;
        const int b = sb >> 3;
        float* Fs  = dyn;                    // [64][33]
        float* Ws2 = dyn + 64*33;            // [192][33]
        int*   pix = (int*)(dyn + 64*33 + 192*33);

        if (tid < 64) pix[tid] = 0;
        __syncthreads();
        if (tid < 32) {
            const int lane = tid;
            int probe = 0;
            #pragma unroll
            for (int i = lane; i < 64; i += 32) probe |= labels[2*(i*512)+1];
            unsigned any = __ballot_sync(0xffffffffu, probe != 0);
            const bool is64 = (any == 0u);
            const long long* L64 = (const long long*)labels;
            int base = 0;
            for (int c = 0; c < 128; c++) {
                if (base >= 64) break;
                int p = (c << 5) + lane;
                long long v = is64 ? L64[(size_t)b*HWN + p]
                                   : (long long)labels[(size_t)b*HWN + p];
                bool valid = (v == 1);
                unsigned m = __ballot_sync(0xffffffffu, valid);
                int pre = __popc(m & ((1u << lane) - 1u));
                if (valid && base + pre < 64) pix[base + pre] = p;
                base += __popc(m);
            }
        }
        __syncthreads();

        float acc[4][12];
        #pragma unroll
        for (int i = 0; i < 4; i++)
            #pragma unroll
            for (int j = 0; j < 12; j++) acc[i][j] = 0.f;

        const int pg = tid & 15;
        const int cg = tid >> 4;
        const size_t fb = (size_t)b*CC*HWN;
        const int kbase = z * 256;

        for (int chn = 0; chn < 8; chn++) {
            int k0 = kbase + chn*32;
            __syncthreads();
            #pragma unroll
            for (int i = 0; i < 8; i++) {
                int idx = tid + i*256;
                int px = idx >> 5, kk = idx & 31;
                Fs[px*33 + kk] = feats[fb + (size_t)(k0+kk)*HWN + pix[px]];
            }
            #pragma unroll
            for (int i = 0; i < 24; i++) {
                int idx = tid + i*256;
                int r = idx >> 5, kk = idx & 31;
                Ws2[r*33 + kk] = (r < 128) ? W1[r*CC + k0 + kk]
                                           : Wa1[(r-128)*CC + k0 + kk];
            }
            __syncthreads();
            #pragma unroll 4
            for (int kk = 0; kk < 32; kk++) {
                float fv[4];
                #pragma unroll
                for (int i = 0; i < 4; i++) fv[i] = Fs[(pg*4 + i)*33 + kk];
                #pragma unroll
                for (int j = 0; j < 12; j++) {
                    float w = Ws2[(cg*12 + j)*33 + kk];
                    #pragma unroll
                    for (int i = 0; i < 4; i++) acc[i][j] += fv[i]*w;
                }
            }
        }
        #pragma unroll
        for (int i = 0; i < 4; i++)
            #pragma unroll
            for (int j = 0; j < 12; j++)
                g_hs8[(size_t)z*196608 + (b*64 + pg*4 + i)*192 + cg*12 + j] = acc[i][j];
        return;
    }

    // ===== conv1 stats: f16 wmma, M=128 x N=128, K-chunk 64 (32 chunks) ==============
    const int cb = blockIdx.x - NSAMPB;
    const int b  = cb >> 5;
    const int p0 = (cb & 31) * 128;
    const float* F = feats + (size_t)b*CC*HWN + p0;

    const int wid = tid >> 5;
    const int wr  = wid & 3;    // 32-pixel group
    const int wc  = wid >> 2;   // 64-channel group

    wmma::fragment<wmma::accumulator,16,16,16,half> acc[2][4];
    #pragma unroll
    for (int i = 0; i < 2; i++)
        #pragma unroll
        for (int j = 0; j < 4; j++) wmma::fill_fragment(acc[i][j], __float2half(0.f));

    auto Ah = [&](int s) { return (half*)(dynC + s*A_STG); };            // [64k][136]
    auto Wh = [&](int s) { return (half*)(dynC + W_OFF + (s)*W_STG); };  // [128ch][72]

    float4 ra[8];
    auto ldA = [&](int kc) {
        const float* Fg = F + (size_t)(kc*64)*HWN;
        #pragma unroll
        for (int i = 0; i < 8; i++) {
            int idx = tid + i*256;
            int k = idx >> 5, px4 = (idx & 31) << 2;
            ra[i] = *reinterpret_cast<const float4*>(Fg + (size_t)k*HWN + px4);
        }
    };
    auto stA = [&](int kc) {
        half* Ab = Ah(kc & 1);
        #pragma unroll
        for (int i = 0; i < 8; i++) {
            int idx = tid + i*256;
            int k = idx >> 5, px4 = (idx & 31) << 2;
            uint2 u; u.x = h2u(ra[i].x, ra[i].y); u.y = h2u(ra[i].z, ra[i].w);
            *reinterpret_cast<uint2*>(Ab + k*136 + px4) = u;
        }
    };
    auto issueW = [&](int kc) {
        half* W = Wh(kc % 3);
        const __half* Wg = g_W1h + kc*64;
        #pragma unroll
        for (int i = 0; i < 4; i++) {
            int idx = tid + i*256;
            int ch = idx >> 3, sg = idx & 7;      // 8 x 16B per 128B row
            cpasync16(W + ch*72 + sg*8, Wg + ch*2048 + sg*8);
        }
        cpcommit();
    };
    auto compute = [&](int kc) {
        const half* Ab = Ah(kc & 1);
        const half* Wb = Wh(kc % 3);
        #pragma unroll
        for (int ks = 0; ks < 64; ks += 16) {
            wmma::fragment<wmma::matrix_a,16,16,16,half,wmma::col_major> af[2];
            #pragma unroll
            for (int i = 0; i < 2; i++)
                wmma::load_matrix_sync(af[i], Ab + ks*136 + wr*32 + i*16, 136);
            wmma::fragment<wmma::matrix_b,16,16,16,half,wmma::col_major> bf[4];
            #pragma unroll
            for (int j = 0; j < 4; j++)
                wmma::load_matrix_sync(bf[j], Wb + (wc*64 + j*16)*72 + ks, 72);
            #pragma unroll
            for (int i = 0; i < 2; i++)
                #pragma unroll
                for (int j = 0; j < 4; j++)
                    wmma::mma_sync(acc[i][j], af[i], bf[j], acc[i][j]);
        }
    };

    issueW(0); issueW(1);
    ldA(0); stA(0);
    ldA(1);
    cpwait<1>();
    __syncthreads();

    for (int kc = 0; kc < 32; kc++) {
        if (kc + 1 < 32) stA(kc + 1);
        if (kc + 2 < 32) ldA(kc + 2);
        compute(kc);
        if (kc + 2 < 32) { issueW(kc + 2); cpwait<1>(); }
        else             { cpwait<0>(); }
        __syncthreads();
    }

    // Epilogue
    half* Cs16 = (half*)dynC;   // [128 px][136]
    #pragma unroll
    for (int i = 0; i < 2; i++)
        #pragma unroll
        for (int j = 0; j < 4; j++)
            wmma::store_matrix_sync(Cs16 + (wr*32 + i*16)*136 + wc*64 + j*16,
                                    acc[i][j], 136, wmma::mem_row_major);
    __syncthreads();
    {
        const int ch = tid & 127;
        const int sg = tid >> 7;
        float s = 0.f, s2 = 0.f;
        #pragma unroll 4
        for (int p = sg*64; p < sg*64 + 64; p++) {
            float v = __half2float(Cs16[p*136 + ch]);
            s += v; s2 += v*v;
        }
        r1[tid] = s; r2[tid] = s2;
        __syncthreads();
        if (tid < 128) {
            g_p1[tid*512 + cb] = r1[tid] + r1[tid+128];
            g_p2[tid*512 + cb] = r2[tid] + r2[tid+128];
        }
    }
}

// ---------------- stats (blocks 0..127) + hs8 reduce (blocks 128..895) ----------------
__global__ __launch_bounds__(256) void k_stats() {
    const int t = threadIdx.x;
    if (blockIdx.x < 128) {
        __shared__ float sS[256], sS2[256];
        const int ch = blockIdx.x;
        if (ch == 0 && t < 16) g_loss[t] = 0.f;
        float S  = g_p1[ch*512 + t] + g_p1[ch*512 + t + 256];
        float S2 = g_p2[ch*512 + t] + g_p2[ch*512 + t + 256];
        sS[t] = S; sS2[t] = S2;
        __syncthreads();
        for (int s = 128; s > 0; s >>= 1) {
            if (t < s) { sS[t] += sS[t+s]; sS2[t] += sS2[t+s]; }
            __syncthreads();
        }
        if (t == 0) {
            float m   = sS[0] * (1.f/65536.f);
            float var = sS2[0] * (1.f/65536.f) - m*m;
            g_mean[ch] = m;
            g_istd[ch] = rsqrtf(var + 1e-5f);
        }
        return;
    }
    int o = (blockIdx.x - 128)*256 + t;
    float h = g_hs8[o];
    #pragma unroll
    for (int z = 1; z < 8; z++) h += g_hs8[(size_t)z*196608 + o];
    g_hs[o] = h;
}

// ---------------- per-pixel: BN + conv2 + normalize + attention ----------------
__global__ void k_proj(const float* __restrict__ b1, const float* __restrict__ gamma,
                       const float* __restrict__ beta, const float* __restrict__ b2,
                       const float* __restrict__ ba1, const float* __restrict__ Wa2,
                       const float* __restrict__ ba2) {
    __shared__ float xr[128];
    __shared__ float ar[64];
    __shared__ float red[128];
    const int t = threadIdx.x;
    const int pid = blockIdx.x;
    {
        float h = g_hs[pid*192 + t] + b1[t];
        float xn = (h - (g_mean[t] + b1[t])) * g_istd[t] * gamma[t] + beta[t];
        xr[t] = fmaxf(xn, 0.f);
    }
    if (t < 64) ar[t] = fmaxf(g_hs[pid*192 + 128 + t] + ba1[t], 0.f);
    __syncthreads();

    float acc = b2[t];
    #pragma unroll 8
    for (int k = 0; k < 128; k++) acc += g_W2t[k*128 + t] * xr[k];

    red[t] = acc*acc;
    __syncthreads();
    for (int s = 64; s > 0; s >>= 1) { if (t < s) red[t] += red[t+s]; __syncthreads(); }
    float rinv = 1.f / fmaxf(sqrtf(red[0]), 1e-12f);
    g_tf[pid*128 + t] = acc * rinv;

    if (t < 32) {
        float z = Wa2[t]*ar[t] + Wa2[t+32]*ar[t+32];
        #pragma unroll
        for (int o = 16; o > 0; o >>= 1) z += __shfl_down_sync(0xffffffffu, z, o);
        if (t == 0) g_tw[pid] = 1.f / (1.f + expf(-(z + ba2[0])));
    }
}

// ---------------- contrastive loss: row-parallel, grid 128 ----------------
__global__ __launch_bounds__(256) void k_loss() {
    __shared__ float tf[64*132];
    __shared__ float tw[64];
    const int t = threadIdx.x;
    const int b  = blockIdx.x >> 3;
    const int rg = blockIdx.x & 7;
    const int wid = t >> 5;
    const int lane = t & 31;

    #pragma unroll
    for (int i = 0; i < 8; i++) {
        int idx = t + i*256;
        int row = idx >> 5, c4 = (idx & 31) << 2;
        float4 v = reinterpret_cast<const float4*>(g_tf + b*8192)[idx];
        *reinterpret_cast<float4*>(tf + row*132 + c4) = v;
    }
    if (t < 64) tw[t] = g_tw[b*64 + t];
    __syncthreads();

    const int i = rg*8 + wid;
    const int j0 = lane, j1 = lane + 32;

    float a0 = 0.f, a1 = 0.f;
    const float4* fi = reinterpret_cast<const float4*>(tf + i*132);
    const float4* c0 = reinterpret_cast<const float4*>(tf + j0*132);
    const float4* c1 = reinterpret_cast<const float4*>(tf + j1*132);
    #pragma unroll 8
    for (int k4 = 0; k4 < 32; k4++) {
        float4 a = fi[k4];
        float4 v0 = c0[k4], v1 = c1[k4];
        a0 += a.x*v0.x + a.y*v0.y + a.z*v0.z + a.w*v0.w;
        a1 += a.x*v1.x + a.y*v1.y + a.z*v1.z + a.w*v1.w;
    }
    float s0 = a0*10.f, s1 = a1*10.f;
    float e0 = expf(s0), e1 = expf(s1);
    float d = e0 + e1;
    #pragma unroll
    for (int o = 16; o > 0; o >>= 1) d += __shfl_xor_sync(0xffffffffu, d, o);

    float twi = tw[i];
    float lacc = 0.f;
    if (s0 > 0.7f && j0 != i) lacc += twi * tw[j0] * logf(e0/d + 1e-10f);
    if (s1 > 0.7f && j1 != i) lacc += twi * tw[j1] * logf(e1/d + 1e-10f);
    #pragma unroll
    for (int o = 16; o > 0; o >>= 1) lacc += __shfl_xor_sync(0xffffffffu, lacc, o);
    if (lane == 0) atomicAdd(&g_loss[b], lacc);
}

// ---------------- final ----------------
__global__ void k_final(float* out) {
    int t = threadIdx.x;
    float v = 0.f;
    if (t < 16) {
        float tsum = 0.f;
        for (int j = 0; j < 64; j++) tsum += g_tw[t*64 + j];
        v = -(0.1f/0.07f) * g_loss[t] / tsum;
    }
    #pragma unroll
    for (int o = 16; o > 0; o >>= 1) v += __shfl_down_sync(0xffffffffu, v, o);
    if (t == 0) out[0] = (v / 16.0f) * 0.1f;
}

// ---------------- launch ----------------
extern "C" void kernel_launch(void* const* d_in, const int* in_sizes, int n_in,
                              void* d_out, int out_size) {
    const float* feats = (const float*)d_in[0];
    const int*   labels= (const int*)d_in[1];
    const float* W1   = (const float*)d_in[2];
    const float* b1   = (const float*)d_in[3];
    const float* gamma= (const float*)d_in[4];
    const float* beta = (const float*)d_in[5];
    const float* W2   = (const float*)d_in[6];
    const float* b2   = (const float*)d_in[7];
    const float* Wa1  = (const float*)d_in[8];
    const float* ba1  = (const float*)d_in[9];
    const float* Wa2  = (const float*)d_in[10];
    const float* ba2  = (const float*)d_in[11];

    cudaFuncSetAttribute(k_fused, cudaFuncAttributeMaxDynamicSharedMemorySize, DYNB);

    k_prep<<<320, 256>>>(W1, W2);
    k_fused<<<NSAMPB + NCONVB, 256, DYNB>>>(feats, W1, Wa1, labels);
    k_stats<<<896, 256>>>();
    k_proj<<<1024, 128>>>(b1, gamma, beta, b2, ba1, Wa2, ba2);
    k_loss<<<128, 256>>>();
    k_final<<<1, 32>>>((float*)d_out);
}

// round 14
// speedup vs baseline: 1.5263x; 1.0204x over previous
#include <cuda_runtime.h>
#include <cuda_fp16.h>
#include <mma.h>
#include <cstdint>

using namespace nvcuda;

#define CC 2048
#define HWN 4096
#define NCONVB 512
#define NSAMPB 128   // 16 img x 8 K-splits

// ---------------- device scratch ----------------
__device__ __half g_W1h[128*2048];
__device__ float g_W2t[128*128];
__device__ float g_p1[128*512];
__device__ float g_p2[128*512];
__device__ float g_mean[128];
__device__ float g_istd[128];
__device__ float g_hs[1024*192];     // accumulated raw dot products (atomicAdd)
__device__ float g_tf[1024*128];
__device__ float g_tw[1024];

// ---------------- helpers ----------------
__device__ __forceinline__ void cpasync16(void* s, const void* g) {
    unsigned sa = (unsigned)__cvta_generic_to_shared(s);
    asm volatile("cp.async.cg.shared.global [%0], [%1], 16;\n" :: "r"(sa), "l"(g));
}
__device__ __forceinline__ void cpcommit() { asm volatile("cp.async.commit_group;\n"); }
template<int N> __device__ __forceinline__ void cpwait() {
    asm volatile("cp.async.wait_group %0;\n" :: "n"(N));
}
__device__ __forceinline__ uint32_t h2u(float x, float y) {
    __half2 h = __floats2half2_rn(x, y);
    return *reinterpret_cast<uint32_t*>(&h);
}

// ---------------- prep: W1 -> half, W2 -> transposed, zero g_hs + out ----------------
__global__ void k_prep(const float* __restrict__ W1, const float* __restrict__ W2,
                       float* out) {
    const int bx = blockIdx.x;
    if (bx == 0 && threadIdx.x == 0) out[0] = 0.f;
    if (bx < 256) {
        int idx = bx*256 + threadIdx.x;
        float4 v = reinterpret_cast<const float4*>(W1)[idx];
        uint2 u; u.x = h2u(v.x, v.y); u.y = h2u(v.z, v.w);
        *reinterpret_cast<uint2*>(g_W1h + idx*4) = u;
    } else if (bx < 320) {
        int idx = (bx - 256)*256 + threadIdx.x;
        int o = idx >> 7, k = idx & 127;
        g_W2t[k*128 + o] = W2[idx];
    } else {
        int idx = (bx - 320)*256 + threadIdx.x;   // 768 blocks x 256 = 196608
        g_hs[idx] = 0.f;
    }
}

// smem: A f16 2 x [64k][136] (17408 B) | W f16 3 x [128ch][72] (18432 B) = 90112 B
#define A_STG 17408
#define W_OFF 34816
#define W_STG 18432
#define DYNB  90112

__global__ __launch_bounds__(256, 2)
void k_fused(const float* __restrict__ feats, const float* __restrict__ W1,
             const float* __restrict__ Wa1,  const int* __restrict__ labels) {
    extern __shared__ char dynC[];
    float* dyn = (float*)dynC;
    __shared__ float r1[256], r2[256];
    const int tid = threadIdx.x;

    if (blockIdx.x < NSAMPB) {
        // ============ sampled path FIRST: exact fp32 conv at 64 label==1 pixels ======
        const int sb = blockIdx.x;
        const int z = sb & 7;
        const int b = sb >> 3;
        float* Fs  = dyn;                    // [64][33]
        float* Ws2 = dyn + 64*33;            // [192][33]
        int*   pix = (int*)(dyn + 64*33 + 192*33);

        if (tid < 64) pix[tid] = 0;
        __syncthreads();
        if (tid < 32) {
            const int lane = tid;
            int probe = 0;
            #pragma unroll
            for (int i = lane; i < 64; i += 32) probe |= labels[2*(i*512)+1];
            unsigned any = __ballot_sync(0xffffffffu, probe != 0);
            const bool is64 = (any == 0u);
            const long long* L64 = (const long long*)labels;
            int base = 0;
            for (int c = 0; c < 128; c++) {
                if (base >= 64) break;
                int p = (c << 5) + lane;
                long long v = is64 ? L64[(size_t)b*HWN + p]
                                   : (long long)labels[(size_t)b*HWN + p];
                bool valid = (v == 1);
                unsigned m = __ballot_sync(0xffffffffu, valid);
                int pre = __popc(m & ((1u << lane) - 1u));
                if (valid && base + pre < 64) pix[base + pre] = p;
                base += __popc(m);
            }
        }
        __syncthreads();

        float acc[4][12];
        #pragma unroll
        for (int i = 0; i < 4; i++)
            #pragma unroll
            for (int j = 0; j < 12; j++) acc[i][j] = 0.f;

        const int pg = tid & 15;
        const int cg = tid >> 4;
        const size_t fb = (size_t)b*CC*HWN;
        const int kbase = z * 256;

        for (int chn = 0; chn < 8; chn++) {
            int k0 = kbase + chn*32;
            __syncthreads();
            #pragma unroll
            for (int i = 0; i < 8; i++) {
                int idx = tid + i*256;
                int px = idx >> 5, kk = idx & 31;
                Fs[px*33 + kk] = feats[fb + (size_t)(k0+kk)*HWN + pix[px]];
            }
            #pragma unroll
            for (int i = 0; i < 24; i++) {
                int idx = tid + i*256;
                int r = idx >> 5, kk = idx & 31;
                Ws2[r*33 + kk] = (r < 128) ? W1[r*CC + k0 + kk]
                                           : Wa1[(r-128)*CC + k0 + kk];
            }
            __syncthreads();
            #pragma unroll 4
            for (int kk = 0; kk < 32; kk++) {
                float fv[4];
                #pragma unroll
                for (int i = 0; i < 4; i++) fv[i] = Fs[(pg*4 + i)*33 + kk];
                #pragma unroll
                for (int j = 0; j < 12; j++) {
                    float w = Ws2[(cg*12 + j)*33 + kk];
                    #pragma unroll
                    for (int i = 0; i < 4; i++) acc[i][j] += fv[i]*w;
                }
            }
        }
        #pragma unroll
        for (int i = 0; i < 4; i++)
            #pragma unroll
            for (int j = 0; j < 12; j++)
                atomicAdd(&g_hs[(b*64 + pg*4 + i)*192 + cg*12 + j], acc[i][j]);
        return;
    }

    // ===== conv1 stats: f16 wmma, M=128 x N=128, K-chunk 64 (32 chunks) ==============
    const int cb = blockIdx.x - NSAMPB;
    const int b  = cb >> 5;
    const int p0 = (cb & 31) * 128;
    const float* F = feats + (size_t)b*CC*HWN + p0;

    const int wid = tid >> 5;
    const int wr  = wid & 3;    // 32-pixel group
    const int wc  = wid >> 2;   // 64-channel group

    wmma::fragment<wmma::accumulator,16,16,16,half> acc[2][4];
    #pragma unroll
    for (int i = 0; i < 2; i++)
        #pragma unroll
        for (int j = 0; j < 4; j++) wmma::fill_fragment(acc[i][j], __float2half(0.f));

    auto Ah = [&](int s) { return (half*)(dynC + s*A_STG); };            // [64k][136]
    auto Wh = [&](int s) { return (half*)(dynC + W_OFF + (s)*W_STG); };  // [128ch][72]

    float4 ra[8];
    auto ldA = [&](int kc) {
        const float* Fg = F + (size_t)(kc*64)*HWN;
        #pragma unroll
        for (int i = 0; i < 8; i++) {
            int idx = tid + i*256;
            int k = idx >> 5, px4 = (idx & 31) << 2;
            ra[i] = *reinterpret_cast<const float4*>(Fg + (size_t)k*HWN + px4);
        }
    };
    auto stA = [&](int kc) {
        half* Ab = Ah(kc & 1);
        #pragma unroll
        for (int i = 0; i < 8; i++) {
            int idx = tid + i*256;
            int k = idx >> 5, px4 = (idx & 31) << 2;
            uint2 u; u.x = h2u(ra[i].x, ra[i].y); u.y = h2u(ra[i].z, ra[i].w);
            *reinterpret_cast<uint2*>(Ab + k*136 + px4) = u;
        }
    };
    auto issueW = [&](int kc) {
        half* W = Wh(kc % 3);
        const __half* Wg = g_W1h + kc*64;
        #pragma unroll
        for (int i = 0; i < 4; i++) {
            int idx = tid + i*256;
            int ch = idx >> 3, sg = idx & 7;
            cpasync16(W + ch*72 + sg*8, Wg + ch*2048 + sg*8);
        }
        cpcommit();
    };
    auto compute = [&](int kc) {
        const half* Ab = Ah(kc & 1);
        const half* Wb = Wh(kc % 3);
        #pragma unroll
        for (int ks = 0; ks < 64; ks += 16) {
            wmma::fragment<wmma::matrix_a,16,16,16,half,wmma::col_major> af[2];
            #pragma unroll
            for (int i = 0; i < 2; i++)
                wmma::load_matrix_sync(af[i], Ab + ks*136 + wr*32 + i*16, 136);
            wmma::fragment<wmma::matrix_b,16,16,16,half,wmma::col_major> bf[4];
            #pragma unroll
            for (int j = 0; j < 4; j++)
                wmma::load_matrix_sync(bf[j], Wb + (wc*64 + j*16)*72 + ks, 72);
            #pragma unroll
            for (int i = 0; i < 2; i++)
                #pragma unroll
                for (int j = 0; j < 4; j++)
                    wmma::mma_sync(acc[i][j], af[i], bf[j], acc[i][j]);
        }
    };

    issueW(0); issueW(1);
    ldA(0); stA(0);
    ldA(1);
    cpwait<1>();
    __syncthreads();

    for (int kc = 0; kc < 32; kc++) {
        if (kc + 1 < 32) stA(kc + 1);
        if (kc + 2 < 32) ldA(kc + 2);
        compute(kc);
        if (kc + 2 < 32) { issueW(kc + 2); cpwait<1>(); }
        else             { cpwait<0>(); }
        __syncthreads();
    }

    // Epilogue
    half* Cs16 = (half*)dynC;   // [128 px][136]
    #pragma unroll
    for (int i = 0; i < 2; i++)
        #pragma unroll
        for (int j = 0; j < 4; j++)
            wmma::store_matrix_sync(Cs16 + (wr*32 + i*16)*136 + wc*64 + j*16,
                                    acc[i][j], 136, wmma::mem_row_major);
    __syncthreads();
    {
        const int ch = tid & 127;
        const int sg = tid >> 7;
        float s = 0.f, s2 = 0.f;
        #pragma unroll 4
        for (int p = sg*64; p < sg*64 + 64; p++) {
            float v = __half2float(Cs16[p*136 + ch]);
            s += v; s2 += v*v;
        }
        r1[tid] = s; r2[tid] = s2;
        __syncthreads();
        if (tid < 128) {
            g_p1[tid*512 + cb] = r1[tid] + r1[tid+128];
            g_p2[tid*512 + cb] = r2[tid] + r2[tid+128];
        }
    }
}

// ---------------- stats: reduce per-block partials (grid 128) ----------------
__global__ __launch_bounds__(256) void k_stats() {
    __shared__ float sS[256], sS2[256];
    const int ch = blockIdx.x;
    const int t = threadIdx.x;
    float S  = g_p1[ch*512 + t] + g_p1[ch*512 + t + 256];
    float S2 = g_p2[ch*512 + t] + g_p2[ch*512 + t + 256];
    sS[t] = S; sS2[t] = S2;
    __syncthreads();
    for (int s = 128; s > 0; s >>= 1) {
        if (t < s) { sS[t] += sS[t+s]; sS2[t] += sS2[t+s]; }
        __syncthreads();
    }
    if (t == 0) {
        float m   = sS[0] * (1.f/65536.f);
        float var = sS2[0] * (1.f/65536.f) - m*m;
        g_mean[ch] = m;
        g_istd[ch] = rsqrtf(var + 1e-5f);
    }
}

// ---------------- per-4-pixel: BN + conv2 + normalize + attention (grid 256) ---------
__global__ __launch_bounds__(256) void k_proj(
        const float* __restrict__ b1, const float* __restrict__ gamma,
        const float* __restrict__ beta, const float* __restrict__ b2,
        const float* __restrict__ ba1, const float* __restrict__ Wa2,
        const float* __restrict__ ba2) {
    __shared__ float xr[4][132];
    __shared__ float ar[4][64];
    __shared__ float redA[256], redB[256];
    const int t = threadIdx.x;
    const int pb = blockIdx.x * 4;      // first pixel of this block

    #pragma unroll
    for (int i = 0; i < 2; i++) {
        int idx = t + i*256;            // < 512
        int px = idx >> 7, ch = idx & 127;
        int pid = pb + px;
        float h = g_hs[pid*192 + ch] + b1[ch];
        float xn = (h - (g_mean[ch] + b1[ch])) * g_istd[ch] * gamma[ch] + beta[ch];
        xr[px][ch] = fmaxf(xn, 0.f);
    }
    {
        int px = t >> 6, ch = t & 63;   // 256 = 4 x 64
        ar[px][ch] = fmaxf(g_hs[(pb + px)*192 + 128 + ch] + ba1[ch], 0.f);
    }
    __syncthreads();

    // conv2: thread = (channel, pixel-pair); each W2t read serves 2 pixels
    const int ch = t & 127;
    const int g  = t >> 7;              // pixel pair g*2, g*2+1
    float accA = b2[ch], accB = b2[ch];
    #pragma unroll 8
    for (int k = 0; k < 128; k++) {
        float w = g_W2t[k*128 + ch];
        accA += w * xr[g*2][k];
        accB += w * xr[g*2+1][k];
    }
    redA[t] = accA*accA;
    redB[t] = accB*accB;
    __syncthreads();
    for (int s = 64; s > 0; s >>= 1) {
        if ((t & 127) < s) { redA[t] += redA[t+s]; redB[t] += redB[t+s]; }
        __syncthreads();
    }
    float rinvA = 1.f / fmaxf(sqrtf(redA[(t & 128)]), 1e-12f);
    float rinvB = 1.f / fmaxf(sqrtf(redB[(t & 128)]), 1e-12f);
    g_tf[(pb + g*2)*128 + ch]   = accA * rinvA;
    g_tf[(pb + g*2+1)*128 + ch] = accB * rinvB;

    if (t < 128) {
        int px = t >> 5, lane = t & 31;
        float z = Wa2[lane]*ar[px][lane] + Wa2[lane+32]*ar[px][lane+32];
        #pragma unroll
        for (int o = 16; o > 0; o >>= 1) z += __shfl_down_sync(0xffffffffu, z, o);
        if (lane == 0) g_tw[pb + px] = 1.f / (1.f + expf(-(z + ba2[0])));
    }
}

// ---------------- contrastive loss + final (grid 128, atomic into out) ---------------
__global__ __launch_bounds__(256) void k_loss(float* out) {
    __shared__ float tf[64*132];
    __shared__ float tw[64];
    __shared__ float red[8];
    const int t = threadIdx.x;
    const int b  = blockIdx.x >> 3;
    const int rg = blockIdx.x & 7;
    const int wid = t >> 5;
    const int lane = t & 31;

    #pragma unroll
    for (int i = 0; i < 8; i++) {
        int idx = t + i*256;
        int row = idx >> 5, c4 = (idx & 31) << 2;
        float4 v = reinterpret_cast<const float4*>(g_tf + b*8192)[idx];
        *reinterpret_cast<float4*>(tf + row*132 + c4) = v;
    }
    if (t < 64) tw[t] = g_tw[b*64 + t];
    __syncthreads();

    const int i = rg*8 + wid;
    const int j0 = lane, j1 = lane + 32;

    float a0 = 0.f, a1 = 0.f;
    const float4* fi = reinterpret_cast<const float4*>(tf + i*132);
    const float4* c0 = reinterpret_cast<const float4*>(tf + j0*132);
    const float4* c1 = reinterpret_cast<const float4*>(tf + j1*132);
    #pragma unroll 8
    for (int k4 = 0; k4 < 32; k4++) {
        float4 a = fi[k4];
        float4 v0 = c0[k4], v1 = c1[k4];
        a0 += a.x*v0.x + a.y*v0.y + a.z*v0.z + a.w*v0.w;
        a1 += a.x*v1.x + a.y*v1.y + a.z*v1.z + a.w*v1.w;
    }
    float s0 = a0*10.f, s1 = a1*10.f;
    float e0 = expf(s0), e1 = expf(s1);
    float d = e0 + e1;
    #pragma unroll
    for (int o = 16; o > 0; o >>= 1) d += __shfl_xor_sync(0xffffffffu, d, o);

    float twi = tw[i];
    float lacc = 0.f;
    if (s0 > 0.7f && j0 != i) lacc += twi * tw[j0] * logf(e0/d + 1e-10f);
    if (s1 > 0.7f && j1 != i) lacc += twi * tw[j1] * logf(e1/d + 1e-10f);
    #pragma unroll
    for (int o = 16; o > 0; o >>= 1) lacc += __shfl_xor_sync(0xffffffffu, lacc, o);
    if (lane == 0) red[wid] = lacc;
    __syncthreads();

    if (t == 0) {
        float blk = red[0]+red[1]+red[2]+red[3]+red[4]+red[5]+red[6]+red[7];
        float tsum = 0.f;
        #pragma unroll 8
        for (int j = 0; j < 64; j++) tsum += tw[j];
        // contribution: mean over 16 images of (-(T/Tb)*loss/tsum) * 0.1
        atomicAdd(out, (-(0.1f/0.07f) * blk / tsum) * (0.1f / 16.0f));
    }
}

// ---------------- launch ----------------
extern "C" void kernel_launch(void* const* d_in, const int* in_sizes, int n_in,
                              void* d_out, int out_size) {
    const float* feats = (const float*)d_in[0];
    const int*   labels= (const int*)d_in[1];
    const float* W1   = (const float*)d_in[2];
    const float* b1   = (const float*)d_in[3];
    const float* gamma= (const float*)d_in[4];
    const float* beta = (const float*)d_in[5];
    const float* W2   = (const float*)d_in[6];
    const float* b2   = (const float*)d_in[7];
    const float* Wa1  = (const float*)d_in[8];
    const float* ba1  = (const float*)d_in[9];
    const float* Wa2  = (const float*)d_in[10];
    const float* ba2  = (const float*)d_in[11];

    cudaFuncSetAttribute(k_fused, cudaFuncAttributeMaxDynamicSharedMemorySize, DYNB);

    k_prep<<<1088, 256>>>(W1, W2, (float*)d_out);
    k_fused<<<NSAMPB + NCONVB, 256, DYNB>>>(feats, W1, Wa1, labels);
    k_stats<<<128, 256>>>();
    k_proj<<<256, 256>>>(b1, gamma, beta, b2, ba1, Wa2, ba2);
    k_loss<<<128, 256>>>((float*)d_out);
}

// round 15
// speedup vs baseline: 1.6298x; 1.0679x over previous
#include <cuda_runtime.h>
#include <cuda_fp16.h>
#include <mma.h>
#include <cstdint>

using namespace nvcuda;

#define CC 2048
#define HWN 4096
#define NCONVB 512
#define NSAMPB 64    // 16 img x 4 K-splits (512 ch each) -> grid 576 = 1.95 waves

// ---------------- device scratch ----------------
__device__ __half g_W1h[128*2048];
__device__ float g_W2t[128*128];
__device__ float g_p1[128*512];
__device__ float g_p2[128*512];
__device__ float g_mean[128];
__device__ float g_istd[128];
__device__ float g_hs[1024*192];     // accumulated raw dot products (atomicAdd)
__device__ float g_tf[1024*128];
__device__ float g_tw[1024];

// ---------------- helpers ----------------
__device__ __forceinline__ void cpasync16(void* s, const void* g) {
    unsigned sa = (unsigned)__cvta_generic_to_shared(s);
    asm volatile("cp.async.cg.shared.global [%0], [%1], 16;\n" :: "r"(sa), "l"(g));
}
__device__ __forceinline__ void cpcommit() { asm volatile("cp.async.commit_group;\n"); }
template<int N> __device__ __forceinline__ void cpwait() {
    asm volatile("cp.async.wait_group %0;\n" :: "n"(N));
}
__device__ __forceinline__ uint32_t h2u(float x, float y) {
    __half2 h = __floats2half2_rn(x, y);
    return *reinterpret_cast<uint32_t*>(&h);
}

// ---------------- prep: W1 -> half, W2 -> transposed, zero g_hs + out ----------------
__global__ void k_prep(const float* __restrict__ W1, const float* __restrict__ W2,
                       float* out) {
    const int bx = blockIdx.x;
    if (bx == 0 && threadIdx.x == 0) out[0] = 0.f;
    if (bx < 256) {
        int idx = bx*256 + threadIdx.x;
        float4 v = reinterpret_cast<const float4*>(W1)[idx];
        uint2 u; u.x = h2u(v.x, v.y); u.y = h2u(v.z, v.w);
        *reinterpret_cast<uint2*>(g_W1h + idx*4) = u;
    } else if (bx < 320) {
        int idx = (bx - 256)*256 + threadIdx.x;
        int o = idx >> 7, k = idx & 127;
        g_W2t[k*128 + o] = W2[idx];
    } else {
        int idx = (bx - 320)*256 + threadIdx.x;   // 768 blocks x 256 = 196608
        g_hs[idx] = 0.f;
    }
}

// smem: A f16 2 x [64k][136] (17408 B) | W f16 3 x [128ch][72] (18432 B) = 90112 B
#define A_STG 17408
#define W_OFF 34816
#define W_STG 18432
#define DYNB  90112

__global__ __launch_bounds__(256, 2)
void k_fused(const float* __restrict__ feats, const float* __restrict__ W1,
             const float* __restrict__ Wa1,  const int* __restrict__ labels) {
    extern __shared__ char dynC[];
    float* dyn = (float*)dynC;
    __shared__ float r1[256], r2[256];
    const int tid = threadIdx.x;

    if (blockIdx.x < NSAMPB) {
        // ============ sampled path FIRST: exact fp32 conv at 64 label==1 pixels ======
        const int sb = blockIdx.x;
        const int z = sb & 3;            // 4 K-splits of 512 channels
        const int b = sb >> 2;
        float* Fs  = dyn;                    // [64][33]
        float* Ws2 = dyn + 64*33;            // [192][33]
        int*   pix = (int*)(dyn + 64*33 + 192*33);

        if (tid < 64) pix[tid] = 0;
        __syncthreads();
        if (tid < 32) {
            const int lane = tid;
            int probe = 0;
            #pragma unroll
            for (int i = lane; i < 64; i += 32) probe |= labels[2*(i*512)+1];
            unsigned any = __ballot_sync(0xffffffffu, probe != 0);
            const bool is64 = (any == 0u);
            const long long* L64 = (const long long*)labels;
            int base = 0;
            for (int c = 0; c < 128; c++) {
                if (base >= 64) break;
                int p = (c << 5) + lane;
                long long v = is64 ? L64[(size_t)b*HWN + p]
                                   : (long long)labels[(size_t)b*HWN + p];
                bool valid = (v == 1);
                unsigned m = __ballot_sync(0xffffffffu, valid);
                int pre = __popc(m & ((1u << lane) - 1u));
                if (valid && base + pre < 64) pix[base + pre] = p;
                base += __popc(m);
            }
        }
        __syncthreads();

        float acc[4][12];
        #pragma unroll
        for (int i = 0; i < 4; i++)
            #pragma unroll
            for (int j = 0; j < 12; j++) acc[i][j] = 0.f;

        const int pg = tid & 15;
        const int cg = tid >> 4;
        const size_t fb = (size_t)b*CC*HWN;
        const int kbase = z * 512;

        for (int chn = 0; chn < 16; chn++) {
            int k0 = kbase + chn*32;
            __syncthreads();
            #pragma unroll
            for (int i = 0; i < 8; i++) {
                int idx = tid + i*256;
                int px = idx >> 5, kk = idx & 31;
                Fs[px*33 + kk] = feats[fb + (size_t)(k0+kk)*HWN + pix[px]];
            }
            #pragma unroll
            for (int i = 0; i < 24; i++) {
                int idx = tid + i*256;
                int r = idx >> 5, kk = idx & 31;
                Ws2[r*33 + kk] = (r < 128) ? W1[r*CC + k0 + kk]
                                           : Wa1[(r-128)*CC + k0 + kk];
            }
            __syncthreads();
            #pragma unroll 4
            for (int kk = 0; kk < 32; kk++) {
                float fv[4];
                #pragma unroll
                for (int i = 0; i < 4; i++) fv[i] = Fs[(pg*4 + i)*33 + kk];
                #pragma unroll
                for (int j = 0; j < 12; j++) {
                    float w = Ws2[(cg*12 + j)*33 + kk];
                    #pragma unroll
                    for (int i = 0; i < 4; i++) acc[i][j] += fv[i]*w;
                }
            }
        }
        #pragma unroll
        for (int i = 0; i < 4; i++)
            #pragma unroll
            for (int j = 0; j < 12; j++)
                atomicAdd(&g_hs[(b*64 + pg*4 + i)*192 + cg*12 + j], acc[i][j]);
        return;
    }

    // ===== conv1 stats: f16 wmma, M=128 x N=128, K-chunk 64 (32 chunks) ==============
    const int cb = blockIdx.x - NSAMPB;
    const int b  = cb >> 5;
    const int p0 = (cb & 31) * 128;
    const float* F = feats + (size_t)b*CC*HWN + p0;

    const int wid = tid >> 5;
    const int wr  = wid & 3;    // 32-pixel group
    const int wc  = wid >> 2;   // 64-channel group

    wmma::fragment<wmma::accumulator,16,16,16,half> acc[2][4];
    #pragma unroll
    for (int i = 0; i < 2; i++)
        #pragma unroll
        for (int j = 0; j < 4; j++) wmma::fill_fragment(acc[i][j], __float2half(0.f));

    auto Ah = [&](int s) { return (half*)(dynC + s*A_STG); };            // [64k][136]
    auto Wh = [&](int s) { return (half*)(dynC + W_OFF + (s)*W_STG); };  // [128ch][72]

    float4 ra[8];
    auto ldA = [&](int kc) {
        const float* Fg = F + (size_t)(kc*64)*HWN;
        #pragma unroll
        for (int i = 0; i < 8; i++) {
            int idx = tid + i*256;
            int k = idx >> 5, px4 = (idx & 31) << 2;
            ra[i] = *reinterpret_cast<const float4*>(Fg + (size_t)k*HWN + px4);
        }
    };
    auto stA = [&](int kc) {
        half* Ab = Ah(kc & 1);
        #pragma unroll
        for (int i = 0; i < 8; i++) {
            int idx = tid + i*256;
            int k = idx >> 5, px4 = (idx & 31) << 2;
            uint2 u; u.x = h2u(ra[i].x, ra[i].y); u.y = h2u(ra[i].z, ra[i].w);
            *reinterpret_cast<uint2*>(Ab + k*136 + px4) = u;
        }
    };
    auto issueW = [&](int kc) {
        half* W = Wh(kc % 3);
        const __half* Wg = g_W1h + kc*64;
        #pragma unroll
        for (int i = 0; i < 4; i++) {
            int idx = tid + i*256;
            int ch = idx >> 3, sg = idx & 7;
            cpasync16(W + ch*72 + sg*8, Wg + ch*2048 + sg*8);
        }
        cpcommit();
    };
    auto compute = [&](int kc) {
        const half* Ab = Ah(kc & 1);
        const half* Wb = Wh(kc % 3);
        #pragma unroll
        for (int ks = 0; ks < 64; ks += 16) {
            wmma::fragment<wmma::matrix_a,16,16,16,half,wmma::col_major> af[2];
            #pragma unroll
            for (int i = 0; i < 2; i++)
                wmma::load_matrix_sync(af[i], Ab + ks*136 + wr*32 + i*16, 136);
            wmma::fragment<wmma::matrix_b,16,16,16,half,wmma::col_major> bf[4];
            #pragma unroll
            for (int j = 0; j < 4; j++)
                wmma::load_matrix_sync(bf[j], Wb + (wc*64 + j*16)*72 + ks, 72);
            #pragma unroll
            for (int i = 0; i < 2; i++)
                #pragma unroll
                for (int j = 0; j < 4; j++)
                    wmma::mma_sync(acc[i][j], af[i], bf[j], acc[i][j]);
        }
    };

    issueW(0); issueW(1);
    ldA(0); stA(0);
    ldA(1);
    cpwait<1>();
    __syncthreads();

    for (int kc = 0; kc < 32; kc++) {
        if (kc + 1 < 32) stA(kc + 1);
        if (kc + 2 < 32) ldA(kc + 2);
        compute(kc);
        if (kc + 2 < 32) { issueW(kc + 2); cpwait<1>(); }
        else             { cpwait<0>(); }
        __syncthreads();
    }

    // Epilogue
    half* Cs16 = (half*)dynC;   // [128 px][136]
    #pragma unroll
    for (int i = 0; i < 2; i++)
        #pragma unroll
        for (int j = 0; j < 4; j++)
            wmma::store_matrix_sync(Cs16 + (wr*32 + i*16)*136 + wc*64 + j*16,
                                    acc[i][j], 136, wmma::mem_row_major);
    __syncthreads();
    {
        const int ch = tid & 127;
        const int sg = tid >> 7;
        float s = 0.f, s2 = 0.f;
        #pragma unroll 4
        for (int p = sg*64; p < sg*64 + 64; p++) {
            float v = __half2float(Cs16[p*136 + ch]);
            s += v; s2 += v*v;
        }
        r1[tid] = s; r2[tid] = s2;
        __syncthreads();
        if (tid < 128) {
            g_p1[tid*512 + cb] = r1[tid] + r1[tid+128];
            g_p2[tid*512 + cb] = r2[tid] + r2[tid+128];
        }
    }
}

// ---------------- stats: reduce per-block partials (grid 128) ----------------
__global__ __launch_bounds__(256) void k_stats() {
    __shared__ float sS[256], sS2[256];
    const int ch = blockIdx.x;
    const int t = threadIdx.x;
    float S  = g_p1[ch*512 + t] + g_p1[ch*512 + t + 256];
    float S2 = g_p2[ch*512 + t] + g_p2[ch*512 + t + 256];
    sS[t] = S; sS2[t] = S2;
    __syncthreads();
    for (int s = 128; s > 0; s >>= 1) {
        if (t < s) { sS[t] += sS[t+s]; sS2[t] += sS2[t+s]; }
        __syncthreads();
    }
    if (t == 0) {
        float m   = sS[0] * (1.f/65536.f);
        float var = sS2[0] * (1.f/65536.f) - m*m;
        g_mean[ch] = m;
        g_istd[ch] = rsqrtf(var + 1e-5f);
    }
}

// ---------------- per-4-pixel: BN + conv2 + normalize + attention (grid 256) ---------
__global__ __launch_bounds__(256) void k_proj(
        const float* __restrict__ b1, const float* __restrict__ gamma,
        const float* __restrict__ beta, const float* __restrict__ b2,
        const float* __restrict__ ba1, const float* __restrict__ Wa2,
        const float* __restrict__ ba2) {
    __shared__ float xr[4][132];
    __shared__ float ar[4][64];
    __shared__ float redA[256], redB[256];
    const int t = threadIdx.x;
    const int pb = blockIdx.x * 4;

    #pragma unroll
    for (int i = 0; i < 2; i++) {
        int idx = t + i*256;
        int px = idx >> 7, ch = idx & 127;
        int pid = pb + px;
        float h = g_hs[pid*192 + ch] + b1[ch];
        float xn = (h - (g_mean[ch] + b1[ch])) * g_istd[ch] * gamma[ch] + beta[ch];
        xr[px][ch] = fmaxf(xn, 0.f);
    }
    {
        int px = t >> 6, ch = t & 63;
        ar[px][ch] = fmaxf(g_hs[(pb + px)*192 + 128 + ch] + ba1[ch], 0.f);
    }
    __syncthreads();

    const int ch = t & 127;
    const int g  = t >> 7;
    float accA = b2[ch], accB = b2[ch];
    #pragma unroll 8
    for (int k = 0; k < 128; k++) {
        float w = g_W2t[k*128 + ch];
        accA += w * xr[g*2][k];
        accB += w * xr[g*2+1][k];
    }
    redA[t] = accA*accA;
    redB[t] = accB*accB;
    __syncthreads();
    for (int s = 64; s > 0; s >>= 1) {
        if ((t & 127) < s) { redA[t] += redA[t+s]; redB[t] += redB[t+s]; }
        __syncthreads();
    }
    float rinvA = 1.f / fmaxf(sqrtf(redA[(t & 128)]), 1e-12f);
    float rinvB = 1.f / fmaxf(sqrtf(redB[(t & 128)]), 1e-12f);
    g_tf[(pb + g*2)*128 + ch]   = accA * rinvA;
    g_tf[(pb + g*2+1)*128 + ch] = accB * rinvB;

    if (t < 128) {
        int px = t >> 5, lane = t & 31;
        float z = Wa2[lane]*ar[px][lane] + Wa2[lane+32]*ar[px][lane+32];
        #pragma unroll
        for (int o = 16; o > 0; o >>= 1) z += __shfl_down_sync(0xffffffffu, z, o);
        if (lane == 0) g_tw[pb + px] = 1.f / (1.f + expf(-(z + ba2[0])));
    }
}

// ---------------- contrastive loss + final (grid 128, atomic into out) ---------------
__global__ __launch_bounds__(256) void k_loss(float* out) {
    __shared__ float tf[64*132];
    __shared__ float tw[64];
    __shared__ float red[8];
    const int t = threadIdx.x;
    const int b  = blockIdx.x >> 3;
    const int rg = blockIdx.x & 7;
    const int wid = t >> 5;
    const int lane = t & 31;

    #pragma unroll
    for (int i = 0; i < 8; i++) {
        int idx = t + i*256;
        int row = idx >> 5, c4 = (idx & 31) << 2;
        float4 v = reinterpret_cast<const float4*>(g_tf + b*8192)[idx];
        *reinterpret_cast<float4*>(tf + row*132 + c4) = v;
    }
    if (t < 64) tw[t] = g_tw[b*64 + t];
    __syncthreads();

    const int i = rg*8 + wid;
    const int j0 = lane, j1 = lane + 32;

    float a0 = 0.f, a1 = 0.f;
    const float4* fi = reinterpret_cast<const float4*>(tf + i*132);
    const float4* c0 = reinterpret_cast<const float4*>(tf + j0*132);
    const float4* c1 = reinterpret_cast<const float4*>(tf + j1*132);
    #pragma unroll 8
    for (int k4 = 0; k4 < 32; k4++) {
        float4 a = fi[k4];
        float4 v0 = c0[k4], v1 = c1[k4];
        a0 += a.x*v0.x + a.y*v0.y + a.z*v0.z + a.w*v0.w;
        a1 += a.x*v1.x + a.y*v1.y + a.z*v1.z + a.w*v1.w;
    }
    float s0 = a0*10.f, s1 = a1*10.f;
    float e0 = expf(s0), e1 = expf(s1);
    float d = e0 + e1;
    #pragma unroll
    for (int o = 16; o > 0; o >>= 1) d += __shfl_xor_sync(0xffffffffu, d, o);

    float twi = tw[i];
    float lacc = 0.f;
    if (s0 > 0.7f && j0 != i) lacc += twi * tw[j0] * logf(e0/d + 1e-10f);
    if (s1 > 0.7f && j1 != i) lacc += twi * tw[j1] * logf(e1/d + 1e-10f);
    #pragma unroll
    for (int o = 16; o > 0; o >>= 1) lacc += __shfl_xor_sync(0xffffffffu, lacc, o);
    if (lane == 0) red[wid] = lacc;
    __syncthreads();

    if (t == 0) {
        float blk = red[0]+red[1]+red[2]+red[3]+red[4]+red[5]+red[6]+red[7];
        float tsum = 0.f;
        #pragma unroll 8
        for (int j = 0; j < 64; j++) tsum += tw[j];
        atomicAdd(out, (-(0.1f/0.07f) * blk / tsum) * (0.1f / 16.0f));
    }
}

// ---------------- launch ----------------
extern "C" void kernel_launch(void* const* d_in, const int* in_sizes, int n_in,
                              void* d_out, int out_size) {
    const float* feats = (const float*)d_in[0];
    const int*   labels= (const int*)d_in[1];
    const float* W1   = (const float*)d_in[2];
    const float* b1   = (const float*)d_in[3];
    const float* gamma= (const float*)d_in[4];
    const float* beta = (const float*)d_in[5];
    const float* W2   = (const float*)d_in[6];
    const float* b2   = (const float*)d_in[7];
    const float* Wa1  = (const float*)d_in[8];
    const float* ba1  = (const float*)d_in[9];
    const float* Wa2  = (const float*)d_in[10];
    const float* ba2  = (const float*)d_in[11];

    cudaFuncSetAttribute(k_fused, cudaFuncAttributeMaxDynamicSharedMemorySize, DYNB);

    k_prep<<<1088, 256>>>(W1, W2, (float*)d_out);
    k_fused<<<NSAMPB + NCONVB, 256, DYNB>>>(feats, W1, Wa1, labels);
    k_stats<<<128, 256>>>();
    k_proj<<<256, 256>>>(b1, gamma, beta, b2, ba1, Wa2, ba2);
    k_loss<<<128, 256>>>((float*)d_out);
}

// round 16
// speedup vs baseline: 1.6717x; 1.0257x over previous
#include <cuda_runtime.h>
#include <cuda_fp16.h>
#include <mma.h>
#include <cstdint>

using namespace nvcuda;

#define CC 2048
#define HWN 4096
#define NCONVB 512
#define NSAMPB 64    // 16 img x 4 K-splits (512 ch each) -> grid 576 = 1.95 waves

// ---------------- device scratch ----------------
__device__ __half g_W1h[128*2048];
__device__ float g_W2t[128*128];
__device__ float g_p1[128*512];
__device__ float g_p2[128*512];
__device__ float g_mean[128];
__device__ float g_istd[128];
__device__ float g_hs[1024*192];     // accumulated raw dot products (atomicAdd)
__device__ float g_tf[1024*128];
__device__ float g_tw[1024];

// ---------------- helpers ----------------
__device__ __forceinline__ void cpasync16(void* s, const void* g) {
    unsigned sa = (unsigned)__cvta_generic_to_shared(s);
    asm volatile("cp.async.cg.shared.global [%0], [%1], 16;\n" :: "r"(sa), "l"(g));
}
__device__ __forceinline__ void cpcommit() { asm volatile("cp.async.commit_group;\n"); }
template<int N> __device__ __forceinline__ void cpwait() {
    asm volatile("cp.async.wait_group %0;\n" :: "n"(N));
}
__device__ __forceinline__ uint32_t h2u(float x, float y) {
    __half2 h = __floats2half2_rn(x, y);
    return *reinterpret_cast<uint32_t*>(&h);
}

// ---------------- prep: W1 -> half, W2 -> transposed, zero g_hs + out ----------------
__global__ void k_prep(const float* __restrict__ W1, const float* __restrict__ W2,
                       float* out) {
    const int bx = blockIdx.x;
    if (bx == 0 && threadIdx.x == 0) out[0] = 0.f;
    if (bx < 256) {
        int idx = bx*256 + threadIdx.x;
        float4 v = reinterpret_cast<const float4*>(W1)[idx];
        uint2 u; u.x = h2u(v.x, v.y); u.y = h2u(v.z, v.w);
        *reinterpret_cast<uint2*>(g_W1h + idx*4) = u;
    } else if (bx < 320) {
        int idx = (bx - 256)*256 + threadIdx.x;
        int o = idx >> 7, k = idx & 127;
        g_W2t[k*128 + o] = W2[idx];
    } else {
        int idx = (bx - 320)*256 + threadIdx.x;   // 768 blocks x 256 = 196608
        g_hs[idx] = 0.f;
    }
}

// smem: A f16 2 x [64k][136] (17408 B) | W f16 3 x [128ch][72] (18432 B) = 90112 B
#define A_STG 17408
#define W_OFF 34816
#define W_STG 18432
#define DYNB  90112

__global__ __launch_bounds__(256, 2)
void k_fused(const float* __restrict__ feats, const float* __restrict__ W1,
             const float* __restrict__ Wa1,  const int* __restrict__ labels) {
    extern __shared__ char dynC[];
    float* dyn = (float*)dynC;
    __shared__ float r1[256], r2[256];
    const int tid = threadIdx.x;

    if (blockIdx.x < NSAMPB) {
        // ============ sampled path FIRST: exact fp32 conv at 64 label==1 pixels ======
        const int sb = blockIdx.x;
        const int z = sb & 3;            // 4 K-splits of 512 channels
        const int b = sb >> 2;
        float* Fs  = dyn;                    // [64][33]
        float* Ws2 = dyn + 64*33;            // [192][33]
        int*   pix = (int*)(dyn + 64*33 + 192*33);

        if (tid < 64) pix[tid] = 0;
        __syncthreads();
        if (tid < 32) {
            const int lane = tid;
            int probe = 0;
            #pragma unroll
            for (int i = lane; i < 64; i += 32) probe |= labels[2*(i*512)+1];
            unsigned any = __ballot_sync(0xffffffffu, probe != 0);
            const bool is64 = (any == 0u);
            const long long* L64 = (const long long*)labels;
            int base = 0;
            for (int c = 0; c < 128; c++) {
                if (base >= 64) break;
                int p = (c << 5) + lane;
                long long v = is64 ? L64[(size_t)b*HWN + p]
                                   : (long long)labels[(size_t)b*HWN + p];
                bool valid = (v == 1);
                unsigned m = __ballot_sync(0xffffffffu, valid);
                int pre = __popc(m & ((1u << lane) - 1u));
                if (valid && base + pre < 64) pix[base + pre] = p;
                base += __popc(m);
            }
        }
        __syncthreads();

        float acc[4][12];
        #pragma unroll
        for (int i = 0; i < 4; i++)
            #pragma unroll
            for (int j = 0; j < 12; j++) acc[i][j] = 0.f;

        const int pg = tid & 15;
        const int cg = tid >> 4;
        const size_t fb = (size_t)b*CC*HWN;
        const int kbase = z * 512;

        for (int chn = 0; chn < 16; chn++) {
            int k0 = kbase + chn*32;
            __syncthreads();
            #pragma unroll
            for (int i = 0; i < 8; i++) {
                int idx = tid + i*256;
                int px = idx >> 5, kk = idx & 31;
                Fs[px*33 + kk] = feats[fb + (size_t)(k0+kk)*HWN + pix[px]];
            }
            #pragma unroll
            for (int i = 0; i < 24; i++) {
                int idx = tid + i*256;
                int r = idx >> 5, kk = idx & 31;
                Ws2[r*33 + kk] = (r < 128) ? W1[r*CC + k0 + kk]
                                           : Wa1[(r-128)*CC + k0 + kk];
            }
            __syncthreads();
            #pragma unroll 4
            for (int kk = 0; kk < 32; kk++) {
                float fv[4];
                #pragma unroll
                for (int i = 0; i < 4; i++) fv[i] = Fs[(pg*4 + i)*33 + kk];
                #pragma unroll
                for (int j = 0; j < 12; j++) {
                    float w = Ws2[(cg*12 + j)*33 + kk];
                    #pragma unroll
                    for (int i = 0; i < 4; i++) acc[i][j] += fv[i]*w;
                }
            }
        }
        #pragma unroll
        for (int i = 0; i < 4; i++)
            #pragma unroll
            for (int j = 0; j < 12; j++)
                atomicAdd(&g_hs[(b*64 + pg*4 + i)*192 + cg*12 + j], acc[i][j]);
        return;
    }

    // ===== conv1 stats: f16 wmma, M=128 x N=128, K-chunk 64 (32 chunks) ==============
    const int cb = blockIdx.x - NSAMPB;
    const int b  = cb >> 5;
    const int p0 = (cb & 31) * 128;
    const float* F = feats + (size_t)b*CC*HWN + p0;

    const int wid = tid >> 5;
    const int wr  = wid & 3;    // 32-pixel group
    const int wc  = wid >> 2;   // 64-channel group

    wmma::fragment<wmma::accumulator,16,16,16,half> acc[2][4];
    #pragma unroll
    for (int i = 0; i < 2; i++)
        #pragma unroll
        for (int j = 0; j < 4; j++) wmma::fill_fragment(acc[i][j], __float2half(0.f));

    auto Ah = [&](int s) { return (half*)(dynC + s*A_STG); };            // [64k][136]
    auto Wh = [&](int s) { return (half*)(dynC + W_OFF + (s)*W_STG); };  // [128ch][72]

    float4 ra[8];
    auto ldA = [&](int kc) {
        const float* Fg = F + (size_t)(kc*64)*HWN;
        #pragma unroll
        for (int i = 0; i < 8; i++) {
            int idx = tid + i*256;
            int k = idx >> 5, px4 = (idx & 31) << 2;
            ra[i] = *reinterpret_cast<const float4*>(Fg + (size_t)k*HWN + px4);
        }
    };
    auto stA = [&](int kc) {
        half* Ab = Ah(kc & 1);
        #pragma unroll
        for (int i = 0; i < 8; i++) {
            int idx = tid + i*256;
            int k = idx >> 5, px4 = (idx & 31) << 2;
            uint2 u; u.x = h2u(ra[i].x, ra[i].y); u.y = h2u(ra[i].z, ra[i].w);
            *reinterpret_cast<uint2*>(Ab + k*136 + px4) = u;
        }
    };
    auto issueW = [&](int kc) {
        half* W = Wh(kc % 3);
        const __half* Wg = g_W1h + kc*64;
        #pragma unroll
        for (int i = 0; i < 4; i++) {
            int idx = tid + i*256;
            int ch = idx >> 3, sg = idx & 7;
            cpasync16(W + ch*72 + sg*8, Wg + ch*2048 + sg*8);
        }
        cpcommit();
    };
    auto compute = [&](int kc) {
        const half* Ab = Ah(kc & 1);
        const half* Wb = Wh(kc % 3);
        #pragma unroll
        for (int ks = 0; ks < 64; ks += 16) {
            wmma::fragment<wmma::matrix_a,16,16,16,half,wmma::col_major> af[2];
            #pragma unroll
            for (int i = 0; i < 2; i++)
                wmma::load_matrix_sync(af[i], Ab + ks*136 + wr*32 + i*16, 136);
            wmma::fragment<wmma::matrix_b,16,16,16,half,wmma::col_major> bf[4];
            #pragma unroll
            for (int j = 0; j < 4; j++)
                wmma::load_matrix_sync(bf[j], Wb + (wc*64 + j*16)*72 + ks, 72);
            #pragma unroll
            for (int i = 0; i < 2; i++)
                #pragma unroll
                for (int j = 0; j < 4; j++)
                    wmma::mma_sync(acc[i][j], af[i], bf[j], acc[i][j]);
        }
    };

    issueW(0); issueW(1);
    ldA(0); stA(0);
    ldA(1);
    cpwait<1>();
    __syncthreads();

    for (int kc = 0; kc < 32; kc++) {
        if (kc + 1 < 32) stA(kc + 1);
        if (kc + 2 < 32) ldA(kc + 2);
        compute(kc);
        if (kc + 2 < 32) { issueW(kc + 2); cpwait<1>(); }
        else             { cpwait<0>(); }
        __syncthreads();
    }

    // Epilogue
    half* Cs16 = (half*)dynC;   // [128 px][136]
    #pragma unroll
    for (int i = 0; i < 2; i++)
        #pragma unroll
        for (int j = 0; j < 4; j++)
            wmma::store_matrix_sync(Cs16 + (wr*32 + i*16)*136 + wc*64 + j*16,
                                    acc[i][j], 136, wmma::mem_row_major);
    __syncthreads();
    {
        const int ch = tid & 127;
        const int sg = tid >> 7;
        float s = 0.f, s2 = 0.f;
        #pragma unroll 4
        for (int p = sg*64; p < sg*64 + 64; p++) {
            float v = __half2float(Cs16[p*136 + ch]);
            s += v; s2 += v*v;
        }
        r1[tid] = s; r2[tid] = s2;
        __syncthreads();
        if (tid < 128) {
            g_p1[tid*512 + cb] = r1[tid] + r1[tid+128];
            g_p2[tid*512 + cb] = r2[tid] + r2[tid+128];
        }
    }
}

// ---------------- stats: reduce per-block partials (grid 128) ----------------
__global__ __launch_bounds__(256) void k_stats() {
    __shared__ float sS[256], sS2[256];
    const int ch = blockIdx.x;
    const int t = threadIdx.x;
    float S  = g_p1[ch*512 + t] + g_p1[ch*512 + t + 256];
    float S2 = g_p2[ch*512 + t] + g_p2[ch*512 + t + 256];
    sS[t] = S; sS2[t] = S2;
    __syncthreads();
    for (int s = 128; s > 0; s >>= 1) {
        if (t < s) { sS[t] += sS[t+s]; sS2[t] += sS2[t+s]; }
        __syncthreads();
    }
    if (t == 0) {
        float m   = sS[0] * (1.f/65536.f);
        float var = sS2[0] * (1.f/65536.f) - m*m;
        g_mean[ch] = m;
        g_istd[ch] = rsqrtf(var + 1e-5f);
    }
}

// ---------------- per-8-pixel proj: W2t staged in smem, grid 128 ----------------
#define PJ_XR 16896            // Ws 128*132
#define PJ_AR (PJ_XR + 8*132)  // xr 8*132
#define PJ_SQ (PJ_AR + 8*64)   // ar 8*64
#define PJ_RI (PJ_SQ + 8*128)  // rsq 8*128
#define PJ_TOT (PJ_RI + 8)     // rinv 8
#define PJ_DYNB (PJ_TOT*4)     // 78104 B

__global__ __launch_bounds__(256) void k_proj(
        const float* __restrict__ b1, const float* __restrict__ gamma,
        const float* __restrict__ beta, const float* __restrict__ b2,
        const float* __restrict__ ba1, const float* __restrict__ Wa2,
        const float* __restrict__ ba2) {
    extern __shared__ float sm[];
    float* Ws  = sm;
    float* xr  = sm + PJ_XR;
    float* ar  = sm + PJ_AR;
    float* rsq = sm + PJ_SQ;
    float* rinv= sm + PJ_RI;
    const int t = threadIdx.x;
    const int pb = blockIdx.x * 8;

    // stage W2t [k][o] -> Ws [k][132]
    #pragma unroll
    for (int i = 0; i < 16; i++) {
        int idx = t + i*256;                // float4 idx < 4096
        int k = idx >> 5, o4 = (idx & 31) << 2;
        float4 v = reinterpret_cast<const float4*>(g_W2t)[idx];
        float* d = Ws + k*132 + o4;
        d[0]=v.x; d[1]=v.y; d[2]=v.z; d[3]=v.w;
    }
    // xr = relu(BN(conv1)) for 8 pixels
    #pragma unroll
    for (int i = 0; i < 4; i++) {
        int idx = t + i*256;                // < 1024
        int px = idx >> 7, ch = idx & 127;
        float h = g_hs[(pb + px)*192 + ch] + b1[ch];
        float xn = (h - (g_mean[ch] + b1[ch])) * g_istd[ch] * gamma[ch] + beta[ch];
        xr[px*132 + ch] = fmaxf(xn, 0.f);
    }
    #pragma unroll
    for (int i = 0; i < 2; i++) {
        int idx = t + i*256;                // < 512
        int px = idx >> 6, ch = idx & 63;
        ar[px*64 + ch] = fmaxf(g_hs[(pb + px)*192 + 128 + ch] + ba1[ch], 0.f);
    }
    __syncthreads();

    // attention: warp w handles pixel w (8 warps = 8 px)
    {
        int px = t >> 5, lane = t & 31;
        float z = Wa2[lane]*ar[px*64 + lane] + Wa2[lane+32]*ar[px*64 + lane+32];
        #pragma unroll
        for (int o = 16; o > 0; o >>= 1) z += __shfl_down_sync(0xffffffffu, z, o);
        if (lane == 0) g_tw[pb + px] = 1.f / (1.f + expf(-(z + ba2[0])));
    }

    // conv2 from smem: thread = (channel, 4-pixel group)
    const int ch  = t & 127;
    const int grp = t >> 7;
    float acc[4];
    #pragma unroll
    for (int j = 0; j < 4; j++) acc[j] = b2[ch];
    #pragma unroll 4
    for (int k = 0; k < 128; k++) {
        float w = Ws[k*132 + ch];
        #pragma unroll
        for (int j = 0; j < 4; j++) acc[j] += w * xr[(grp*4 + j)*132 + k];
    }
    #pragma unroll
    for (int j = 0; j < 4; j++) rsq[(grp*4 + j)*128 + ch] = acc[j]*acc[j];
    __syncthreads();
    {
        int px = t >> 5, lane = t & 31;
        float s = rsq[px*128 + lane] + rsq[px*128 + lane+32]
                + rsq[px*128 + lane+64] + rsq[px*128 + lane+96];
        #pragma unroll
        for (int o = 16; o > 0; o >>= 1) s += __shfl_down_sync(0xffffffffu, s, o);
        if (lane == 0) rinv[px] = 1.f / fmaxf(sqrtf(s), 1e-12f);
    }
    __syncthreads();
    #pragma unroll
    for (int j = 0; j < 4; j++)
        g_tf[(pb + grp*4 + j)*128 + ch] = acc[j] * rinv[grp*4 + j];
}

// ---------------- contrastive loss + final (grid 128, atomic into out) ---------------
__global__ __launch_bounds__(256) void k_loss(float* out) {
    __shared__ float tf[64*132];
    __shared__ float tw[64];
    __shared__ float red[8];
    const int t = threadIdx.x;
    const int b  = blockIdx.x >> 3;
    const int rg = blockIdx.x & 7;
    const int wid = t >> 5;
    const int lane = t & 31;

    #pragma unroll
    for (int i = 0; i < 8; i++) {
        int idx = t + i*256;
        int row = idx >> 5, c4 = (idx & 31) << 2;
        float4 v = reinterpret_cast<const float4*>(g_tf + b*8192)[idx];
        *reinterpret_cast<float4*>(tf + row*132 + c4) = v;
    }
    if (t < 64) tw[t] = g_tw[b*64 + t];
    __syncthreads();

    const int i = rg*8 + wid;
    const int j0 = lane, j1 = lane + 32;

    float a0 = 0.f, a1 = 0.f;
    const float4* fi = reinterpret_cast<const float4*>(tf + i*132);
    const float4* c0 = reinterpret_cast<const float4*>(tf + j0*132);
    const float4* c1 = reinterpret_cast<const float4*>(tf + j1*132);
    #pragma unroll 8
    for (int k4 = 0; k4 < 32; k4++) {
        float4 a = fi[k4];
        float4 v0 = c0[k4], v1 = c1[k4];
        a0 += a.x*v0.x + a.y*v0.y + a.z*v0.z + a.w*v0.w;
        a1 += a.x*v1.x + a.y*v1.y + a.z*v1.z + a.w*v1.w;
    }
    float s0 = a0*10.f, s1 = a1*10.f;
    float e0 = expf(s0), e1 = expf(s1);
    float d = e0 + e1;
    #pragma unroll
    for (int o = 16; o > 0; o >>= 1) d += __shfl_xor_sync(0xffffffffu, d, o);

    float twi = tw[i];
    float lacc = 0.f;
    if (s0 > 0.7f && j0 != i) lacc += twi * tw[j0] * logf(e0/d + 1e-10f);
    if (s1 > 0.7f && j1 != i) lacc += twi * tw[j1] * logf(e1/d + 1e-10f);
    #pragma unroll
    for (int o = 16; o > 0; o >>= 1) lacc += __shfl_xor_sync(0xffffffffu, lacc, o);
    if (lane == 0) red[wid] = lacc;
    __syncthreads();

    if (t == 0) {
        float blk = red[0]+red[1]+red[2]+red[3]+red[4]+red[5]+red[6]+red[7];
        float tsum = 0.f;
        #pragma unroll 8
        for (int j = 0; j < 64; j++) tsum += tw[j];
        atomicAdd(out, (-(0.1f/0.07f) * blk / tsum) * (0.1f / 16.0f));
    }
}

// ---------------- launch ----------------
extern "C" void kernel_launch(void* const* d_in, const int* in_sizes, int n_in,
                              void* d_out, int out_size) {
    const float* feats = (const float*)d_in[0];
    const int*   labels= (const int*)d_in[1];
    const float* W1   = (const float*)d_in[2];
    const float* b1   = (const float*)d_in[3];
    const float* gamma= (const float*)d_in[4];
    const float* beta = (const float*)d_in[5];
    const float* W2   = (const float*)d_in[6];
    const float* b2   = (const float*)d_in[7];
    const float* Wa1  = (const float*)d_in[8];
    const float* ba1  = (const float*)d_in[9];
    const float* Wa2  = (const float*)d_in[10];
    const float* ba2  = (const float*)d_in[11];

    cudaFuncSetAttribute(k_fused, cudaFuncAttributeMaxDynamicSharedMemorySize, DYNB);
    cudaFuncSetAttribute(k_proj,  cudaFuncAttributeMaxDynamicSharedMemorySize, PJ_DYNB);

    k_prep<<<1088, 256>>>(W1, W2, (float*)d_out);
    k_fused<<<NSAMPB + NCONVB, 256, DYNB>>>(feats, W1, Wa1, labels);
    k_stats<<<128, 256>>>();
    k_proj<<<128, 256, PJ_DYNB>>>(b1, gamma, beta, b2, ba1, Wa2, ba2);
    k_loss<<<128, 256>>>((float*)d_out);
}